// round 1
// baseline (speedup 1.0000x reference)
#include <cuda_runtime.h>
#include <math.h>

#define NSEQ 4096
#define T 128
#define Dd 8
#define Rr 32
#define ENC_H 64
#define NH 64
#define KM 10
#define KPAD 16

#define GRP 8
#define SEQ_PER_BLOCK 32
#define THREADS (GRP * SEQ_PER_BLOCK)   // 256
#define NBLOCKS (NSEQ / SEQ_PER_BLOCK)  // 128

struct SmemT {
    float A[Rr * Dd * Rr];        // 8192  A[i][d][j]
    float W1[Rr * NH];            // 2048  nade1_w[i][o]
    float W2[NH * NH];            // 4096  nade2_w[j][o]
    float Head[3][KPAD][68];      // transposed: Head[h][k][j] = W[j][k], padded
    float Enc2T[Dd][68];          // Enc2T[d][i] = enc2_w[i][d], padded
    float B1[NH];
    float B2[NH];
    float Hb[3][KPAD];
    float E1w[ENC_H];
    float E1b[ENC_H];
    float E2b[Dd];
    float Init[Rr];
};

__global__ void __launch_bounds__(THREADS) wfa_kernel(
    const float* __restrict__ x,
    const float* __restrict__ enc1_w, const float* __restrict__ enc1_b,
    const float* __restrict__ enc2_w, const float* __restrict__ enc2_b,
    const float* __restrict__ A_g,
    const float* __restrict__ init_w,
    const float* __restrict__ n1w, const float* __restrict__ n1b,
    const float* __restrict__ n2w, const float* __restrict__ n2b,
    const float* __restrict__ mu_w, const float* __restrict__ mu_b,
    const float* __restrict__ sg_w, const float* __restrict__ sg_b,
    const float* __restrict__ al_w, const float* __restrict__ al_b,
    float* __restrict__ out)
{
    extern __shared__ float smem_raw[];
    SmemT* S = reinterpret_cast<SmemT*>(smem_raw);
    const int tid = threadIdx.x;

    // ---- stage weights into shared ----
    for (int i = tid; i < Rr * Dd * Rr; i += THREADS) S->A[i]  = A_g[i];
    for (int i = tid; i < Rr * NH;      i += THREADS) S->W1[i] = n1w[i];
    for (int i = tid; i < NH * NH;      i += THREADS) S->W2[i] = n2w[i];
    for (int i = tid; i < 3 * KPAD * 68; i += THREADS) {
        int j = i % 68; int k = (i / 68) % KPAD; int h = i / (68 * KPAD);
        float v = 0.0f;
        if (j < NH && k < KM) {
            const float* W = (h == 0) ? mu_w : ((h == 1) ? sg_w : al_w);
            v = W[j * KM + k];
        }
        (&S->Head[0][0][0])[i] = v;
    }
    for (int i = tid; i < Dd * 68; i += THREADS) {
        int j = i % 68; int d = i / 68;
        (&S->Enc2T[0][0])[i] = (j < ENC_H) ? enc2_w[j * Dd + d] : 0.0f;
    }
    if (tid < NH) {
        S->B1[tid]  = n1b[tid];
        S->B2[tid]  = n2b[tid];
        S->E1w[tid] = enc1_w[tid];
        S->E1b[tid] = enc1_b[tid];
    }
    if (tid < 3 * KPAD) {
        int k = tid % KPAD; int h = tid / KPAD;
        float v;
        if (k < KM) v = ((h == 0) ? mu_b : ((h == 1) ? sg_b : al_b))[k];
        else        v = (h == 2) ? -1e30f : 0.0f;
        (&S->Hb[0][0])[tid] = v;
    }
    if (tid < Dd) S->E2b[tid] = enc2_b[tid];
    if (tid < Rr) S->Init[tid] = init_w[tid];
    __syncthreads();

    const unsigned FULL = 0xffffffffu;
    const int g = tid & 7;                       // lane within group of 8
    const int n = blockIdx.x * SEQ_PER_BLOCK + (tid >> 3);
    const float* xr = x + n * T;
    const float HALF_LOG2PI = 0.9189385332046727f;

    // state: tmp[4g..4g+3] on this lane
    float tmp[4];
    #pragma unroll
    for (int c = 0; c < 4; c++) tmp[c] = S->Init[4 * g + c];
    float res = 0.0f;
    float x_prev = 0.0f;

    #pragma unroll 1
    for (int t = 0; t < T; t++) {
        const float xt = __ldg(&xr[t]);

        if (t > 0) {
            // ---- encoder on x_{t-1}: e[g] (each lane computes its own dim) ----
            float eacc = S->E2b[g];
            const float* e2 = &S->Enc2T[g][0];
            #pragma unroll
            for (int i = 0; i < ENC_H; i += 4) {
                float4 wv = *(const float4*)&S->E1w[i];
                float4 bv = *(const float4*)&S->E1b[i];
                float4 tv = *(const float4*)&e2[i];
                eacc += fmaxf(fmaf(x_prev, wv.x, bv.x), 0.0f) * tv.x;
                eacc += fmaxf(fmaf(x_prev, wv.y, bv.y), 0.0f) * tv.y;
                eacc += fmaxf(fmaf(x_prev, wv.z, bv.z), 0.0f) * tv.z;
                eacc += fmaxf(fmaf(x_prev, wv.w, bv.w), 0.0f) * tv.w;
            }
            const float el = tanhf(eacc);
            float er[8];
            #pragma unroll
            for (int d = 0; d < 8; d++) er[d] = __shfl_sync(FULL, el, d, 8);

            // ---- einsum: tmp_new[j] = sum_d e[d] * sum_i tmp[i] * A[i][d][j] ----
            float C[32];   // C[d*4+cc] = sum_i tmp[i]*A[i][d][4g+cc]
            #pragma unroll
            for (int q = 0; q < 32; q++) C[q] = 0.0f;
            #pragma unroll
            for (int gg = 0; gg < 8; gg++) {
                float tv0 = __shfl_sync(FULL, tmp[0], gg, 8);
                float tv1 = __shfl_sync(FULL, tmp[1], gg, 8);
                float tv2 = __shfl_sync(FULL, tmp[2], gg, 8);
                float tv3 = __shfl_sync(FULL, tmp[3], gg, 8);
                float tv[4] = {tv0, tv1, tv2, tv3};
                #pragma unroll
                for (int c = 0; c < 4; c++) {
                    const int i = gg * 4 + c;
                    const float* Ar = &S->A[i * (Dd * Rr) + 4 * g];
                    #pragma unroll
                    for (int d = 0; d < 8; d++) {
                        float4 av = *(const float4*)&Ar[d * Rr];
                        C[d * 4 + 0] = fmaf(tv[c], av.x, C[d * 4 + 0]);
                        C[d * 4 + 1] = fmaf(tv[c], av.y, C[d * 4 + 1]);
                        C[d * 4 + 2] = fmaf(tv[c], av.z, C[d * 4 + 2]);
                        C[d * 4 + 3] = fmaf(tv[c], av.w, C[d * 4 + 3]);
                    }
                }
            }
            #pragma unroll
            for (int c = 0; c < 4; c++) {
                float s = er[0] * C[c];
                #pragma unroll
                for (int d = 1; d < 8; d++) s = fmaf(er[d], C[d * 4 + c], s);
                tmp[c] = s;
            }
        }

        // ---- phi(xt, tmp) ----
        float th[4];
        #pragma unroll
        for (int c = 0; c < 4; c++) th[c] = tanhf(tmp[c]);

        // h1[8g..8g+7]
        float h1[8];
        #pragma unroll
        for (int o = 0; o < 8; o++) h1[o] = S->B1[8 * g + o];
        #pragma unroll
        for (int gg = 0; gg < 8; gg++) {
            float tv0 = __shfl_sync(FULL, th[0], gg, 8);
            float tv1 = __shfl_sync(FULL, th[1], gg, 8);
            float tv2 = __shfl_sync(FULL, th[2], gg, 8);
            float tv3 = __shfl_sync(FULL, th[3], gg, 8);
            float tv[4] = {tv0, tv1, tv2, tv3};
            #pragma unroll
            for (int c = 0; c < 4; c++) {
                const int i = gg * 4 + c;
                float4 wa = *(const float4*)&S->W1[i * NH + 8 * g];
                float4 wb = *(const float4*)&S->W1[i * NH + 8 * g + 4];
                h1[0] = fmaf(tv[c], wa.x, h1[0]); h1[1] = fmaf(tv[c], wa.y, h1[1]);
                h1[2] = fmaf(tv[c], wa.z, h1[2]); h1[3] = fmaf(tv[c], wa.w, h1[3]);
                h1[4] = fmaf(tv[c], wb.x, h1[4]); h1[5] = fmaf(tv[c], wb.y, h1[5]);
                h1[6] = fmaf(tv[c], wb.z, h1[6]); h1[7] = fmaf(tv[c], wb.w, h1[7]);
            }
        }
        #pragma unroll
        for (int o = 0; o < 8; o++) h1[o] = fmaxf(h1[o], 0.0f);

        // h2[8g..8g+7]
        float h2[8];
        #pragma unroll
        for (int o = 0; o < 8; o++) h2[o] = S->B2[8 * g + o];
        #pragma unroll
        for (int gg = 0; gg < 8; gg++) {
            float hv[8];
            #pragma unroll
            for (int c = 0; c < 8; c++) hv[c] = __shfl_sync(FULL, h1[c], gg, 8);
            #pragma unroll
            for (int c = 0; c < 8; c++) {
                const int j = gg * 8 + c;
                float4 wa = *(const float4*)&S->W2[j * NH + 8 * g];
                float4 wb = *(const float4*)&S->W2[j * NH + 8 * g + 4];
                h2[0] = fmaf(hv[c], wa.x, h2[0]); h2[1] = fmaf(hv[c], wa.y, h2[1]);
                h2[2] = fmaf(hv[c], wa.z, h2[2]); h2[3] = fmaf(hv[c], wa.w, h2[3]);
                h2[4] = fmaf(hv[c], wb.x, h2[4]); h2[5] = fmaf(hv[c], wb.y, h2[5]);
                h2[6] = fmaf(hv[c], wb.z, h2[6]); h2[7] = fmaf(hv[c], wb.w, h2[7]);
            }
        }
        #pragma unroll
        for (int o = 0; o < 8; o++) h2[o] = fmaxf(h2[o], 0.0f);

        // heads: this lane owns components k0=g, k1=g+8 (k>=10 masked via -1e30 alpha bias)
        float m0 = S->Hb[0][g], m1 = S->Hb[0][g + 8];
        float s0 = S->Hb[1][g], s1 = S->Hb[1][g + 8];
        float a0 = S->Hb[2][g], a1 = S->Hb[2][g + 8];
        #pragma unroll
        for (int gg = 0; gg < 8; gg++) {
            float hv[8];
            #pragma unroll
            for (int c = 0; c < 8; c++) hv[c] = __shfl_sync(FULL, h2[c], gg, 8);
            const int j0 = gg * 8;
            #pragma unroll
            for (int half = 0; half < 2; half++) {
                const int jb = j0 + 4 * half;
                const float* hp = hv + 4 * half;
                float4 q;
                q = *(const float4*)&S->Head[0][g][jb];
                m0 = fmaf(hp[0], q.x, m0); m0 = fmaf(hp[1], q.y, m0);
                m0 = fmaf(hp[2], q.z, m0); m0 = fmaf(hp[3], q.w, m0);
                q = *(const float4*)&S->Head[0][g + 8][jb];
                m1 = fmaf(hp[0], q.x, m1); m1 = fmaf(hp[1], q.y, m1);
                m1 = fmaf(hp[2], q.z, m1); m1 = fmaf(hp[3], q.w, m1);
                q = *(const float4*)&S->Head[1][g][jb];
                s0 = fmaf(hp[0], q.x, s0); s0 = fmaf(hp[1], q.y, s0);
                s0 = fmaf(hp[2], q.z, s0); s0 = fmaf(hp[3], q.w, s0);
                q = *(const float4*)&S->Head[1][g + 8][jb];
                s1 = fmaf(hp[0], q.x, s1); s1 = fmaf(hp[1], q.y, s1);
                s1 = fmaf(hp[2], q.z, s1); s1 = fmaf(hp[3], q.w, s1);
                q = *(const float4*)&S->Head[2][g][jb];
                a0 = fmaf(hp[0], q.x, a0); a0 = fmaf(hp[1], q.y, a0);
                a0 = fmaf(hp[2], q.z, a0); a0 = fmaf(hp[3], q.w, a0);
                q = *(const float4*)&S->Head[2][g + 8][jb];
                a1 = fmaf(hp[0], q.x, a1); a1 = fmaf(hp[1], q.y, a1);
                a1 = fmaf(hp[2], q.z, a1); a1 = fmaf(hp[3], q.w, a1);
            }
        }

        // mixture log-density:
        // lse_k(alpha_k + comp_k) - lse_k(alpha_k)
        const float is0 = expf(-s0), is1 = expf(-s1);
        const float z0 = (xt - m0) * is0, z1 = (xt - m1) * is1;
        const float c0 = a0 - 0.5f * z0 * z0 - s0 - HALF_LOG2PI;
        const float c1 = a1 - 0.5f * z1 * z1 - s1 - HALF_LOG2PI;

        float ma = fmaxf(a0, a1);
        float mc = fmaxf(c0, c1);
        #pragma unroll
        for (int o = 4; o >= 1; o >>= 1) {
            ma = fmaxf(ma, __shfl_xor_sync(FULL, ma, o, 8));
            mc = fmaxf(mc, __shfl_xor_sync(FULL, mc, o, 8));
        }
        float sa = expf(a0 - ma) + expf(a1 - ma);
        float sc = expf(c0 - mc) + expf(c1 - mc);
        #pragma unroll
        for (int o = 4; o >= 1; o >>= 1) {
            sa += __shfl_xor_sync(FULL, sa, o, 8);
            sc += __shfl_xor_sync(FULL, sc, o, 8);
        }
        res += (mc + logf(sc)) - (ma + logf(sa));

        x_prev = xt;
    }

    if (g == 0) out[n] = expf(res);
}

extern "C" void kernel_launch(void* const* d_in, const int* in_sizes, int n_in,
                              void* d_out, int out_size) {
    const float* x      = (const float*)d_in[0];
    const float* enc1_w = (const float*)d_in[1];
    const float* enc1_b = (const float*)d_in[2];
    const float* enc2_w = (const float*)d_in[3];
    const float* enc2_b = (const float*)d_in[4];
    const float* A      = (const float*)d_in[5];
    const float* init_w = (const float*)d_in[6];
    const float* n1w    = (const float*)d_in[7];
    const float* n1b    = (const float*)d_in[8];
    const float* n2w    = (const float*)d_in[9];
    const float* n2b    = (const float*)d_in[10];
    const float* mu_w   = (const float*)d_in[11];
    const float* mu_b   = (const float*)d_in[12];
    const float* sg_w   = (const float*)d_in[13];
    const float* sg_b   = (const float*)d_in[14];
    const float* al_w   = (const float*)d_in[15];
    const float* al_b   = (const float*)d_in[16];
    float* out = (float*)d_out;

    cudaFuncSetAttribute(wfa_kernel, cudaFuncAttributeMaxDynamicSharedMemorySize,
                         (int)sizeof(SmemT));
    wfa_kernel<<<NBLOCKS, THREADS, sizeof(SmemT)>>>(
        x, enc1_w, enc1_b, enc2_w, enc2_b, A, init_w,
        n1w, n1b, n2w, n2b, mu_w, mu_b, sg_w, sg_b, al_w, al_b, out);
}

// round 2
// speedup vs baseline: 1.6394x; 1.6394x over previous
#include <cuda_runtime.h>
#include <math.h>

#define NSEQ 4096
#define T 128
#define Dd 8
#define Rr 32
#define ENC_H 64
#define NH 64
#define KM 10
#define KPAD 16

#define GRP 8
#define SEQ_PER_BLOCK 32          // 16 groups * 2 seqs
#define THREADS 128               // 16 groups of 8 lanes
#define NBLOCKS (NSEQ / SEQ_PER_BLOCK)  // 128

struct SmemT {
    float A[Rr * Dd * Rr];        // A[i][d][j]
    float W1[Rr * NH];            // nade1_w[i][o]
    float W2[NH * NH];            // nade2_w[j][o]
    float Head[3][KPAD][68];      // Head[h][k][j] = W[j][k], padded
    float Enc2T[Dd][68];          // Enc2T[d][i] = enc2_w[i][d], padded
    float B1[NH];
    float B2[NH];
    float Hb[3][KPAD];
    float E1w[ENC_H];
    float E1b[ENC_H];
    float E2b[Dd];
    float Init[Rr];
};

__global__ void __launch_bounds__(THREADS) wfa_kernel(
    const float* __restrict__ x,
    const float* __restrict__ enc1_w, const float* __restrict__ enc1_b,
    const float* __restrict__ enc2_w, const float* __restrict__ enc2_b,
    const float* __restrict__ A_g,
    const float* __restrict__ init_w,
    const float* __restrict__ n1w, const float* __restrict__ n1b,
    const float* __restrict__ n2w, const float* __restrict__ n2b,
    const float* __restrict__ mu_w, const float* __restrict__ mu_b,
    const float* __restrict__ sg_w, const float* __restrict__ sg_b,
    const float* __restrict__ al_w, const float* __restrict__ al_b,
    float* __restrict__ out)
{
    extern __shared__ float smem_raw[];
    SmemT* S = reinterpret_cast<SmemT*>(smem_raw);
    const int tid = threadIdx.x;

    // ---- stage weights into shared ----
    for (int i = tid; i < Rr * Dd * Rr; i += THREADS) S->A[i]  = A_g[i];
    for (int i = tid; i < Rr * NH;      i += THREADS) S->W1[i] = n1w[i];
    for (int i = tid; i < NH * NH;      i += THREADS) S->W2[i] = n2w[i];
    for (int i = tid; i < 3 * KPAD * 68; i += THREADS) {
        int j = i % 68; int k = (i / 68) % KPAD; int h = i / (68 * KPAD);
        float v = 0.0f;
        if (j < NH && k < KM) {
            const float* W = (h == 0) ? mu_w : ((h == 1) ? sg_w : al_w);
            v = W[j * KM + k];
        }
        (&S->Head[0][0][0])[i] = v;
    }
    for (int i = tid; i < Dd * 68; i += THREADS) {
        int j = i % 68; int d = i / 68;
        (&S->Enc2T[0][0])[i] = (j < ENC_H) ? enc2_w[j * Dd + d] : 0.0f;
    }
    if (tid < NH) {
        S->B1[tid]  = n1b[tid];
        S->B2[tid]  = n2b[tid];
        S->E1w[tid] = enc1_w[tid];
        S->E1b[tid] = enc1_b[tid];
    }
    if (tid < 3 * KPAD) {
        int k = tid % KPAD; int h = tid / KPAD;
        float v;
        if (k < KM) v = ((h == 0) ? mu_b : ((h == 1) ? sg_b : al_b))[k];
        else        v = (h == 2) ? -1e30f : 0.0f;
        (&S->Hb[0][0])[tid] = v;
    }
    if (tid < Dd) S->E2b[tid] = enc2_b[tid];
    if (tid < Rr) S->Init[tid] = init_w[tid];
    __syncthreads();

    const unsigned FULL = 0xffffffffu;
    const int g = tid & 7;              // lane within group of 8
    const int grp = tid >> 3;           // group 0..15
    const int n0 = blockIdx.x * SEQ_PER_BLOCK + grp * 2;
    const float* xr0 = x + n0 * T;
    const float* xr1 = xr0 + T;
    const float HALF_LOG2PI = 0.9189385332046727f;

    // per-lane state: tmp[4g..4g+3] for each of 2 seqs
    float tmp0[4], tmp1[4];
    #pragma unroll
    for (int c = 0; c < 4; c++) { tmp0[c] = S->Init[4 * g + c]; tmp1[c] = tmp0[c]; }
    float res0 = 0.0f, res1 = 0.0f;
    float xp0 = 0.0f, xp1 = 0.0f;

    #pragma unroll 1
    for (int t = 0; t < T; t++) {
        const float xt0 = __ldg(&xr0[t]);
        const float xt1 = __ldg(&xr1[t]);

        if (t > 0) {
            // ---- encoder on x_prev for both seqs: lane computes dim g ----
            float a0a = 0.0f, a0b = 0.0f, a1a = 0.0f, a1b = 0.0f;
            const float* e2 = &S->Enc2T[g][0];
            #pragma unroll
            for (int i = 0; i < ENC_H; i += 8) {
                float4 wv0 = *(const float4*)&S->E1w[i];
                float4 bv0 = *(const float4*)&S->E1b[i];
                float4 tv0v = *(const float4*)&e2[i];
                float4 wv1 = *(const float4*)&S->E1w[i + 4];
                float4 bv1 = *(const float4*)&S->E1b[i + 4];
                float4 tv1v = *(const float4*)&e2[i + 4];
                a0a += fmaxf(fmaf(xp0, wv0.x, bv0.x), 0.0f) * tv0v.x;
                a0a += fmaxf(fmaf(xp0, wv0.y, bv0.y), 0.0f) * tv0v.y;
                a0a += fmaxf(fmaf(xp0, wv0.z, bv0.z), 0.0f) * tv0v.z;
                a0a += fmaxf(fmaf(xp0, wv0.w, bv0.w), 0.0f) * tv0v.w;
                a0b += fmaxf(fmaf(xp0, wv1.x, bv1.x), 0.0f) * tv1v.x;
                a0b += fmaxf(fmaf(xp0, wv1.y, bv1.y), 0.0f) * tv1v.y;
                a0b += fmaxf(fmaf(xp0, wv1.z, bv1.z), 0.0f) * tv1v.z;
                a0b += fmaxf(fmaf(xp0, wv1.w, bv1.w), 0.0f) * tv1v.w;
                a1a += fmaxf(fmaf(xp1, wv0.x, bv0.x), 0.0f) * tv0v.x;
                a1a += fmaxf(fmaf(xp1, wv0.y, bv0.y), 0.0f) * tv0v.y;
                a1a += fmaxf(fmaf(xp1, wv0.z, bv0.z), 0.0f) * tv0v.z;
                a1a += fmaxf(fmaf(xp1, wv0.w, bv0.w), 0.0f) * tv0v.w;
                a1b += fmaxf(fmaf(xp1, wv1.x, bv1.x), 0.0f) * tv1v.x;
                a1b += fmaxf(fmaf(xp1, wv1.y, bv1.y), 0.0f) * tv1v.y;
                a1b += fmaxf(fmaf(xp1, wv1.z, bv1.z), 0.0f) * tv1v.z;
                a1b += fmaxf(fmaf(xp1, wv1.w, bv1.w), 0.0f) * tv1v.w;
            }
            const float el0 = tanhf(a0a + a0b + S->E2b[g]);
            const float el1 = tanhf(a1a + a1b + S->E2b[g]);
            float er0[8], er1[8];
            #pragma unroll
            for (int d = 0; d < 8; d++) {
                er0[d] = __shfl_sync(FULL, el0, d, 8);
                er1[d] = __shfl_sync(FULL, el1, d, 8);
            }

            // ---- einsum: C[b][d*4+cc] = sum_i tmp[b][i]*A[i][d][4g+cc] ----
            float C0[32], C1[32];
            #pragma unroll
            for (int q = 0; q < 32; q++) { C0[q] = 0.0f; C1[q] = 0.0f; }
            #pragma unroll 1
            for (int gg = 0; gg < 8; gg++) {
                float tv0[4], tv1[4];
                #pragma unroll
                for (int c = 0; c < 4; c++) {
                    tv0[c] = __shfl_sync(FULL, tmp0[c], gg, 8);
                    tv1[c] = __shfl_sync(FULL, tmp1[c], gg, 8);
                }
                const float* Ab = &S->A[gg * 4 * (Dd * Rr) + 4 * g];
                #pragma unroll
                for (int c = 0; c < 4; c++) {
                    const float* Ar = Ab + c * (Dd * Rr);
                    #pragma unroll
                    for (int d = 0; d < 8; d++) {
                        float4 av = *(const float4*)&Ar[d * Rr];
                        C0[d * 4 + 0] = fmaf(tv0[c], av.x, C0[d * 4 + 0]);
                        C0[d * 4 + 1] = fmaf(tv0[c], av.y, C0[d * 4 + 1]);
                        C0[d * 4 + 2] = fmaf(tv0[c], av.z, C0[d * 4 + 2]);
                        C0[d * 4 + 3] = fmaf(tv0[c], av.w, C0[d * 4 + 3]);
                        C1[d * 4 + 0] = fmaf(tv1[c], av.x, C1[d * 4 + 0]);
                        C1[d * 4 + 1] = fmaf(tv1[c], av.y, C1[d * 4 + 1]);
                        C1[d * 4 + 2] = fmaf(tv1[c], av.z, C1[d * 4 + 2]);
                        C1[d * 4 + 3] = fmaf(tv1[c], av.w, C1[d * 4 + 3]);
                    }
                }
            }
            #pragma unroll
            for (int c = 0; c < 4; c++) {
                float s0 = er0[0] * C0[c];
                float s1 = er1[0] * C1[c];
                #pragma unroll
                for (int d = 1; d < 8; d++) {
                    s0 = fmaf(er0[d], C0[d * 4 + c], s0);
                    s1 = fmaf(er1[d], C1[d * 4 + c], s1);
                }
                tmp0[c] = s0; tmp1[c] = s1;
            }
        }

        // ---- phi for both seqs ----
        float th0[4], th1[4];
        #pragma unroll
        for (int c = 0; c < 4; c++) { th0[c] = tanhf(tmp0[c]); th1[c] = tanhf(tmp1[c]); }

        // h1[8g..8g+7] per seq
        float h10[8], h11[8];
        #pragma unroll
        for (int o = 0; o < 8; o++) { h10[o] = S->B1[8 * g + o]; h11[o] = h10[o]; }
        #pragma unroll 1
        for (int gg = 0; gg < 8; gg++) {
            float tv0[4], tv1[4];
            #pragma unroll
            for (int c = 0; c < 4; c++) {
                tv0[c] = __shfl_sync(FULL, th0[c], gg, 8);
                tv1[c] = __shfl_sync(FULL, th1[c], gg, 8);
            }
            const float* Wb = &S->W1[gg * 4 * NH + 8 * g];
            #pragma unroll
            for (int c = 0; c < 4; c++) {
                float4 wa = *(const float4*)&Wb[c * NH];
                float4 wb = *(const float4*)&Wb[c * NH + 4];
                h10[0] = fmaf(tv0[c], wa.x, h10[0]); h10[1] = fmaf(tv0[c], wa.y, h10[1]);
                h10[2] = fmaf(tv0[c], wa.z, h10[2]); h10[3] = fmaf(tv0[c], wa.w, h10[3]);
                h10[4] = fmaf(tv0[c], wb.x, h10[4]); h10[5] = fmaf(tv0[c], wb.y, h10[5]);
                h10[6] = fmaf(tv0[c], wb.z, h10[6]); h10[7] = fmaf(tv0[c], wb.w, h10[7]);
                h11[0] = fmaf(tv1[c], wa.x, h11[0]); h11[1] = fmaf(tv1[c], wa.y, h11[1]);
                h11[2] = fmaf(tv1[c], wa.z, h11[2]); h11[3] = fmaf(tv1[c], wa.w, h11[3]);
                h11[4] = fmaf(tv1[c], wb.x, h11[4]); h11[5] = fmaf(tv1[c], wb.y, h11[5]);
                h11[6] = fmaf(tv1[c], wb.z, h11[6]); h11[7] = fmaf(tv1[c], wb.w, h11[7]);
            }
        }
        #pragma unroll
        for (int o = 0; o < 8; o++) { h10[o] = fmaxf(h10[o], 0.0f); h11[o] = fmaxf(h11[o], 0.0f); }

        // h2[8g..8g+7] per seq
        float h20[8], h21[8];
        #pragma unroll
        for (int o = 0; o < 8; o++) { h20[o] = S->B2[8 * g + o]; h21[o] = h20[o]; }
        #pragma unroll 1
        for (int gg = 0; gg < 8; gg++) {
            float hv0[8], hv1[8];
            #pragma unroll
            for (int c = 0; c < 8; c++) {
                hv0[c] = __shfl_sync(FULL, h10[c], gg, 8);
                hv1[c] = __shfl_sync(FULL, h11[c], gg, 8);
            }
            const float* Wb = &S->W2[gg * 8 * NH + 8 * g];
            #pragma unroll
            for (int c = 0; c < 8; c++) {
                float4 wa = *(const float4*)&Wb[c * NH];
                float4 wb = *(const float4*)&Wb[c * NH + 4];
                h20[0] = fmaf(hv0[c], wa.x, h20[0]); h20[1] = fmaf(hv0[c], wa.y, h20[1]);
                h20[2] = fmaf(hv0[c], wa.z, h20[2]); h20[3] = fmaf(hv0[c], wa.w, h20[3]);
                h20[4] = fmaf(hv0[c], wb.x, h20[4]); h20[5] = fmaf(hv0[c], wb.y, h20[5]);
                h20[6] = fmaf(hv0[c], wb.z, h20[6]); h20[7] = fmaf(hv0[c], wb.w, h20[7]);
                h21[0] = fmaf(hv1[c], wa.x, h21[0]); h21[1] = fmaf(hv1[c], wa.y, h21[1]);
                h21[2] = fmaf(hv1[c], wa.z, h21[2]); h21[3] = fmaf(hv1[c], wa.w, h21[3]);
                h21[4] = fmaf(hv1[c], wb.x, h21[4]); h21[5] = fmaf(hv1[c], wb.y, h21[5]);
                h21[6] = fmaf(hv1[c], wb.z, h21[6]); h21[7] = fmaf(hv1[c], wb.w, h21[7]);
            }
        }
        #pragma unroll
        for (int o = 0; o < 8; o++) { h20[o] = fmaxf(h20[o], 0.0f); h21[o] = fmaxf(h21[o], 0.0f); }

        // heads: lane owns components k=g and k=g+8 for both seqs
        float m00 = S->Hb[0][g], m10 = S->Hb[0][g + 8];
        float s00 = S->Hb[1][g], s10 = S->Hb[1][g + 8];
        float a00 = S->Hb[2][g], a10 = S->Hb[2][g + 8];
        float m01 = m00, m11 = m10, s01 = s00, s11 = s10, a01 = a00, a11 = a10;
        #pragma unroll 1
        for (int gg = 0; gg < 8; gg++) {
            float hv0[8], hv1[8];
            #pragma unroll
            for (int c = 0; c < 8; c++) {
                hv0[c] = __shfl_sync(FULL, h20[c], gg, 8);
                hv1[c] = __shfl_sync(FULL, h21[c], gg, 8);
            }
            const int j0 = gg * 8;
            #pragma unroll
            for (int half = 0; half < 2; half++) {
                const int jb = j0 + 4 * half;
                const float* hp0 = hv0 + 4 * half;
                const float* hp1 = hv1 + 4 * half;
                float4 q;
                q = *(const float4*)&S->Head[0][g][jb];
                m00 = fmaf(hp0[0], q.x, m00); m00 = fmaf(hp0[1], q.y, m00);
                m00 = fmaf(hp0[2], q.z, m00); m00 = fmaf(hp0[3], q.w, m00);
                m01 = fmaf(hp1[0], q.x, m01); m01 = fmaf(hp1[1], q.y, m01);
                m01 = fmaf(hp1[2], q.z, m01); m01 = fmaf(hp1[3], q.w, m01);
                q = *(const float4*)&S->Head[0][g + 8][jb];
                m10 = fmaf(hp0[0], q.x, m10); m10 = fmaf(hp0[1], q.y, m10);
                m10 = fmaf(hp0[2], q.z, m10); m10 = fmaf(hp0[3], q.w, m10);
                m11 = fmaf(hp1[0], q.x, m11); m11 = fmaf(hp1[1], q.y, m11);
                m11 = fmaf(hp1[2], q.z, m11); m11 = fmaf(hp1[3], q.w, m11);
                q = *(const float4*)&S->Head[1][g][jb];
                s00 = fmaf(hp0[0], q.x, s00); s00 = fmaf(hp0[1], q.y, s00);
                s00 = fmaf(hp0[2], q.z, s00); s00 = fmaf(hp0[3], q.w, s00);
                s01 = fmaf(hp1[0], q.x, s01); s01 = fmaf(hp1[1], q.y, s01);
                s01 = fmaf(hp1[2], q.z, s01); s01 = fmaf(hp1[3], q.w, s01);
                q = *(const float4*)&S->Head[1][g + 8][jb];
                s10 = fmaf(hp0[0], q.x, s10); s10 = fmaf(hp0[1], q.y, s10);
                s10 = fmaf(hp0[2], q.z, s10); s10 = fmaf(hp0[3], q.w, s10);
                s11 = fmaf(hp1[0], q.x, s11); s11 = fmaf(hp1[1], q.y, s11);
                s11 = fmaf(hp1[2], q.z, s11); s11 = fmaf(hp1[3], q.w, s11);
                q = *(const float4*)&S->Head[2][g][jb];
                a00 = fmaf(hp0[0], q.x, a00); a00 = fmaf(hp0[1], q.y, a00);
                a00 = fmaf(hp0[2], q.z, a00); a00 = fmaf(hp0[3], q.w, a00);
                a01 = fmaf(hp1[0], q.x, a01); a01 = fmaf(hp1[1], q.y, a01);
                a01 = fmaf(hp1[2], q.z, a01); a01 = fmaf(hp1[3], q.w, a01);
                q = *(const float4*)&S->Head[2][g + 8][jb];
                a10 = fmaf(hp0[0], q.x, a10); a10 = fmaf(hp0[1], q.y, a10);
                a10 = fmaf(hp0[2], q.z, a10); a10 = fmaf(hp0[3], q.w, a10);
                a11 = fmaf(hp1[0], q.x, a11); a11 = fmaf(hp1[1], q.y, a11);
                a11 = fmaf(hp1[2], q.z, a11); a11 = fmaf(hp1[3], q.w, a11);
            }
        }

        // ---- mixture log-density for both seqs ----
        {
            const float is0 = __expf(-s00), is1 = __expf(-s10);
            const float z0 = (xt0 - m00) * is0, z1 = (xt0 - m10) * is1;
            const float c0 = a00 - 0.5f * z0 * z0 - s00 - HALF_LOG2PI;
            const float c1 = a10 - 0.5f * z1 * z1 - s10 - HALF_LOG2PI;
            float ma = fmaxf(a00, a10);
            float mc = fmaxf(c0, c1);
            #pragma unroll
            for (int o = 4; o >= 1; o >>= 1) {
                ma = fmaxf(ma, __shfl_xor_sync(FULL, ma, o, 8));
                mc = fmaxf(mc, __shfl_xor_sync(FULL, mc, o, 8));
            }
            float sa = __expf(a00 - ma) + __expf(a10 - ma);
            float sc = __expf(c0 - mc) + __expf(c1 - mc);
            #pragma unroll
            for (int o = 4; o >= 1; o >>= 1) {
                sa += __shfl_xor_sync(FULL, sa, o, 8);
                sc += __shfl_xor_sync(FULL, sc, o, 8);
            }
            res0 += (mc + __logf(sc)) - (ma + __logf(sa));
        }
        {
            const float is0 = __expf(-s01), is1 = __expf(-s11);
            const float z0 = (xt1 - m01) * is0, z1 = (xt1 - m11) * is1;
            const float c0 = a01 - 0.5f * z0 * z0 - s01 - HALF_LOG2PI;
            const float c1 = a11 - 0.5f * z1 * z1 - s11 - HALF_LOG2PI;
            float ma = fmaxf(a01, a11);
            float mc = fmaxf(c0, c1);
            #pragma unroll
            for (int o = 4; o >= 1; o >>= 1) {
                ma = fmaxf(ma, __shfl_xor_sync(FULL, ma, o, 8));
                mc = fmaxf(mc, __shfl_xor_sync(FULL, mc, o, 8));
            }
            float sa = __expf(a01 - ma) + __expf(a11 - ma);
            float sc = __expf(c0 - mc) + __expf(c1 - mc);
            #pragma unroll
            for (int o = 4; o >= 1; o >>= 1) {
                sa += __shfl_xor_sync(FULL, sa, o, 8);
                sc += __shfl_xor_sync(FULL, sc, o, 8);
            }
            res1 += (mc + __logf(sc)) - (ma + __logf(sa));
        }

        xp0 = xt0;
        xp1 = xt1;
    }

    if (g == 0) {
        out[n0]     = expf(res0);
        out[n0 + 1] = expf(res1);
    }
}

extern "C" void kernel_launch(void* const* d_in, const int* in_sizes, int n_in,
                              void* d_out, int out_size) {
    const float* x      = (const float*)d_in[0];
    const float* enc1_w = (const float*)d_in[1];
    const float* enc1_b = (const float*)d_in[2];
    const float* enc2_w = (const float*)d_in[3];
    const float* enc2_b = (const float*)d_in[4];
    const float* A      = (const float*)d_in[5];
    const float* init_w = (const float*)d_in[6];
    const float* n1w    = (const float*)d_in[7];
    const float* n1b    = (const float*)d_in[8];
    const float* n2w    = (const float*)d_in[9];
    const float* n2b    = (const float*)d_in[10];
    const float* mu_w   = (const float*)d_in[11];
    const float* mu_b   = (const float*)d_in[12];
    const float* sg_w   = (const float*)d_in[13];
    const float* sg_b   = (const float*)d_in[14];
    const float* al_w   = (const float*)d_in[15];
    const float* al_b   = (const float*)d_in[16];
    float* out = (float*)d_out;

    cudaFuncSetAttribute(wfa_kernel, cudaFuncAttributeMaxDynamicSharedMemorySize,
                         (int)sizeof(SmemT));
    wfa_kernel<<<NBLOCKS, THREADS, sizeof(SmemT)>>>(
        x, enc1_w, enc1_b, enc2_w, enc2_b, A, init_w,
        n1w, n1b, n2w, n2b, mu_w, mu_b, sg_w, sg_b, al_w, al_b, out);
}

// round 3
// speedup vs baseline: 2.4511x; 1.4951x over previous
#include <cuda_runtime.h>
#include <math.h>

#define NSEQ 4096
#define T 128
#define THREADS 128
#define NBLOCKS 128
#define SEQ_PER_WARP 8

// ---- f32x2 packed helpers ----
typedef unsigned long long F2;

__device__ __forceinline__ F2 pk2(float lo, float hi) {
    F2 r; asm("mov.b64 %0,{%1,%2};" : "=l"(r) : "f"(lo), "f"(hi)); return r;
}
__device__ __forceinline__ void upk2(F2 v, float& lo, float& hi) {
    asm("mov.b64 {%0,%1},%2;" : "=f"(lo), "=f"(hi) : "l"(v));
}
__device__ __forceinline__ F2 fma2(F2 a, F2 b, F2 c) {
    F2 d; asm("fma.rn.f32x2 %0,%1,%2,%3;" : "=l"(d) : "l"(a), "l"(b), "l"(c)); return d;
}
__device__ __forceinline__ F2 dup2(float w) { return pk2(w, w); }

__device__ __forceinline__ float tanh_fast(float x) {
    float e = __expf(2.0f * x);
    return 1.0f - __fdividef(2.0f, e + 1.0f);
}

// ---- shared memory layout (float offsets) ----
#define OFF_A    0        // A[i][d][j]            8192
#define OFF_W1   8192     // nade1_w[i][o]         2048
#define OFF_W2   10240    // nade2_w[k][o]         4096
#define OFF_HW   14336    // HW[j][c] c:0..29 pad32  2048
#define OFF_E1W  16384    // 64
#define OFF_E1B  16448    // 64
#define OFF_E2T  16512    // Enc2T[d][i] 8x68      544
#define OFF_E2B  17056    // 8
#define OFF_B1   17064    // 64
#define OFF_B2   17128    // 64
#define OFF_INIT 17192    // 32
#define OFF_HB   17224    // 32
#define W_TOT    17256

// per-warp activation scratch (float offsets inside warp block)
#define ACT_TMP  0        // F2 [np][32]   256 floats
#define ACT_TH   256      // F2 [np][32]   256
#define ACT_H1   512      // F2 [np][64]   512
#define ACT_H2   1024     // F2 [np][64]   512
#define ACT_E    1536     // F2 [np][8]    64
#define ACT_HD   1600     // F2 [np][32]   256
#define WARP_ACT 1856

#define SMEM_FLOATS (W_TOT + 4 * WARP_ACT)

__global__ void __launch_bounds__(THREADS, 1) wfa_kernel(
    const float* __restrict__ x,
    const float* __restrict__ enc1_w, const float* __restrict__ enc1_b,
    const float* __restrict__ enc2_w, const float* __restrict__ enc2_b,
    const float* __restrict__ A_g,
    const float* __restrict__ init_w,
    const float* __restrict__ n1w, const float* __restrict__ n1b,
    const float* __restrict__ n2w, const float* __restrict__ n2b,
    const float* __restrict__ mu_w, const float* __restrict__ mu_b,
    const float* __restrict__ sg_w, const float* __restrict__ sg_b,
    const float* __restrict__ al_w, const float* __restrict__ al_b,
    float* __restrict__ out)
{
    extern __shared__ float sm[];
    const int tid = threadIdx.x;

    // ---- stage weights ----
    for (int i = tid; i < 8192; i += THREADS) sm[OFF_A + i]  = A_g[i];
    for (int i = tid; i < 2048; i += THREADS) sm[OFF_W1 + i] = n1w[i];
    for (int i = tid; i < 4096; i += THREADS) sm[OFF_W2 + i] = n2w[i];
    for (int i = tid; i < 2048; i += THREADS) {
        int j = i >> 5, c = i & 31;
        float v = 0.0f;
        if (c < 10)      v = mu_w[j * 10 + c];
        else if (c < 20) v = sg_w[j * 10 + (c - 10)];
        else if (c < 30) v = al_w[j * 10 + (c - 20)];
        sm[OFF_HW + i] = v;
    }
    for (int i = tid; i < 544; i += THREADS) {
        int d = i / 68, ii = i % 68;
        sm[OFF_E2T + i] = (ii < 64) ? enc2_w[ii * 8 + d] : 0.0f;
    }
    if (tid < 64) {
        sm[OFF_E1W + tid] = enc1_w[tid];
        sm[OFF_E1B + tid] = enc1_b[tid];
        sm[OFF_B1 + tid]  = n1b[tid];
        sm[OFF_B2 + tid]  = n2b[tid];
    }
    if (tid < 8)  sm[OFF_E2B + tid]  = enc2_b[tid];
    if (tid < 32) sm[OFF_INIT + tid] = init_w[tid];
    if (tid < 32) {
        int c = tid; float v = 0.0f;
        if (c < 10)      v = mu_b[c];
        else if (c < 20) v = sg_b[c - 10];
        else if (c < 30) v = al_b[c - 20];
        sm[OFF_HB + c] = v;
    }
    __syncthreads();

    const int wid = tid >> 5;
    const int l   = tid & 31;
    const int n_lane = l & 7;          // seq handled by this lane (enc/mixture)
    const int np_l   = n_lane >> 1;    // pair index of n_lane
    const int pe     = n_lane & 1;     // element within pair
    const int d0     = l >> 3;         // encoder d slice: d0 and d0+4

    float* act = sm + W_TOT + wid * WARP_ACT;
    F2* tmpS  = (F2*)(act + ACT_TMP);   // [np*32 + j]
    F2* thS   = (F2*)(act + ACT_TH);    // [np*32 + i]
    F2* h1S   = (F2*)(act + ACT_H1);    // [np*64 + o]
    F2* h2S   = (F2*)(act + ACT_H2);    // [np*64 + o]
    F2* eS    = (F2*)(act + ACT_E);     // [np*8 + d]
    F2* hdS   = (F2*)(act + ACT_HD);    // [np*32 + c]
    float* eSf = (float*)eS;
    float* hdf = (float*)hdS;

    const float* SA  = sm + OFF_A;
    const float* SW1 = sm + OFF_W1;
    const float* SW2 = sm + OFF_W2;
    const float* SHW = sm + OFF_HW;

    const int n0 = blockIdx.x * 32 + wid * SEQ_PER_WARP;
    const float* xrow = x + (n0 + n_lane) * T;
    const float HALF_LOG2PI = 0.9189385332046727f;

    // ---- init state: lane owns j = l for all 8 seqs (4 pairs) ----
    F2 tmpP[4];
    {
        float iv = sm[OFF_INIT + l];
        #pragma unroll
        for (int np = 0; np < 4; np++) { tmpP[np] = dup2(iv); tmpS[np * 32 + l] = tmpP[np]; }
    }
    __syncwarp();

    float res = 0.0f;
    float xp = 0.0f;

    #pragma unroll 1
    for (int t = 0; t < T; t++) {
        const float xt = __ldg(&xrow[t]);

        if (t > 0) {
            // ===== encoder: lane computes e[n_lane][d0] and e[n_lane][d0+4] =====
            float acc0 = 0.0f, acc1 = 0.0f;
            const float* Et0 = sm + OFF_E2T + d0 * 68;
            const float* Et1 = Et0 + 4 * 68;
            #pragma unroll 4
            for (int i = 0; i < 64; i += 4) {
                float4 w = *(const float4*)&sm[OFF_E1W + i];
                float4 b = *(const float4*)&sm[OFF_E1B + i];
                float4 t0 = *(const float4*)&Et0[i];
                float4 t1 = *(const float4*)&Et1[i];
                float h;
                h = fmaxf(fmaf(xp, w.x, b.x), 0.0f); acc0 = fmaf(h, t0.x, acc0); acc1 = fmaf(h, t1.x, acc1);
                h = fmaxf(fmaf(xp, w.y, b.y), 0.0f); acc0 = fmaf(h, t0.y, acc0); acc1 = fmaf(h, t1.y, acc1);
                h = fmaxf(fmaf(xp, w.z, b.z), 0.0f); acc0 = fmaf(h, t0.z, acc0); acc1 = fmaf(h, t1.z, acc1);
                h = fmaxf(fmaf(xp, w.w, b.w), 0.0f); acc0 = fmaf(h, t0.w, acc0); acc1 = fmaf(h, t1.w, acc1);
            }
            const float e0 = tanh_fast(acc0 + sm[OFF_E2B + d0]);
            const float e1 = tanh_fast(acc1 + sm[OFF_E2B + d0 + 4]);
            __syncwarp();
            eSf[(np_l * 8 + d0) * 2 + pe]     = e0;
            eSf[(np_l * 8 + d0 + 4) * 2 + pe] = e1;
            __syncwarp();

            // ===== einsum: u[np][d] = sum_i tmp[np][i] * A[i][d][l] =====
            F2 u[32];
            #pragma unroll
            for (int q = 0; q < 32; q++) u[q] = 0ULL;
            #pragma unroll 2
            for (int ii = 0; ii < 16; ii++) {
                const int i = ii * 2;
                F2 tva[4], tvb[4];
                #pragma unroll
                for (int np = 0; np < 4; np++) {
                    ulonglong2 v = *(const ulonglong2*)&tmpS[np * 32 + i];
                    tva[np] = v.x; tvb[np] = v.y;
                }
                const float* Ar = SA + i * 256 + l;
                #pragma unroll
                for (int d = 0; d < 8; d++) {
                    F2 ap = dup2(Ar[d * 32]);
                    F2 bp = dup2(Ar[256 + d * 32]);
                    #pragma unroll
                    for (int np = 0; np < 4; np++) {
                        u[np * 8 + d] = fma2(tva[np], ap, u[np * 8 + d]);
                        u[np * 8 + d] = fma2(tvb[np], bp, u[np * 8 + d]);
                    }
                }
            }
            // combine with e: tmp_new[np] = sum_d e[np][d] * u[np][d]
            F2 nt[4] = {0ULL, 0ULL, 0ULL, 0ULL};
            #pragma unroll
            for (int d = 0; d < 8; d += 2) {
                #pragma unroll
                for (int np = 0; np < 4; np++) {
                    ulonglong2 ev = *(const ulonglong2*)&eS[np * 8 + d];
                    nt[np] = fma2(ev.x, u[np * 8 + d], nt[np]);
                    nt[np] = fma2(ev.y, u[np * 8 + d + 1], nt[np]);
                }
            }
            __syncwarp();   // all lanes finished reading old tmpS
            #pragma unroll
            for (int np = 0; np < 4; np++) { tmpP[np] = nt[np]; tmpS[np * 32 + l] = nt[np]; }
            __syncwarp();
        }

        // ===== phi =====
        // tanh of state
        #pragma unroll
        for (int np = 0; np < 4; np++) {
            float a, b; upk2(tmpP[np], a, b);
            thS[np * 32 + l] = pk2(tanh_fast(a), tanh_fast(b));
        }
        __syncwarp();

        // --- W1: 32 -> 64, lane owns o = 2l, 2l+1 ---
        F2 h1P[2][4];
        {
            float b0 = sm[OFF_B1 + 2 * l], b1 = sm[OFF_B1 + 2 * l + 1];
            #pragma unroll
            for (int np = 0; np < 4; np++) { h1P[0][np] = dup2(b0); h1P[1][np] = dup2(b1); }
        }
        #pragma unroll 2
        for (int ii = 0; ii < 16; ii++) {
            const int i = ii * 2;
            F2 ta[4], tb[4];
            #pragma unroll
            for (int np = 0; np < 4; np++) {
                ulonglong2 v = *(const ulonglong2*)&thS[np * 32 + i];
                ta[np] = v.x; tb[np] = v.y;
            }
            float2 w0 = *(const float2*)&SW1[i * 64 + 2 * l];
            float2 w1 = *(const float2*)&SW1[(i + 1) * 64 + 2 * l];
            F2 w00 = dup2(w0.x), w01 = dup2(w0.y), w10 = dup2(w1.x), w11 = dup2(w1.y);
            #pragma unroll
            for (int np = 0; np < 4; np++) {
                h1P[0][np] = fma2(ta[np], w00, h1P[0][np]);
                h1P[1][np] = fma2(ta[np], w01, h1P[1][np]);
                h1P[0][np] = fma2(tb[np], w10, h1P[0][np]);
                h1P[1][np] = fma2(tb[np], w11, h1P[1][np]);
            }
        }
        // relu + store h1S[np][o] (o = 2l, 2l+1 contiguous -> STS.128 per np)
        #pragma unroll
        for (int np = 0; np < 4; np++) {
            float a, b;
            upk2(h1P[0][np], a, b); F2 p0 = pk2(fmaxf(a, 0.0f), fmaxf(b, 0.0f));
            upk2(h1P[1][np], a, b); F2 p1 = pk2(fmaxf(a, 0.0f), fmaxf(b, 0.0f));
            ulonglong2 st; st.x = p0; st.y = p1;
            *(ulonglong2*)&h1S[np * 64 + 2 * l] = st;
        }
        __syncwarp();

        // --- W2: 64 -> 64 ---
        F2 h2P[2][4];
        {
            float b0 = sm[OFF_B2 + 2 * l], b1 = sm[OFF_B2 + 2 * l + 1];
            #pragma unroll
            for (int np = 0; np < 4; np++) { h2P[0][np] = dup2(b0); h2P[1][np] = dup2(b1); }
        }
        #pragma unroll 2
        for (int kk = 0; kk < 32; kk++) {
            const int k = kk * 2;
            F2 ha[4], hb[4];
            #pragma unroll
            for (int np = 0; np < 4; np++) {
                ulonglong2 v = *(const ulonglong2*)&h1S[np * 64 + k];
                ha[np] = v.x; hb[np] = v.y;
            }
            float2 w0 = *(const float2*)&SW2[k * 64 + 2 * l];
            float2 w1 = *(const float2*)&SW2[(k + 1) * 64 + 2 * l];
            F2 w00 = dup2(w0.x), w01 = dup2(w0.y), w10 = dup2(w1.x), w11 = dup2(w1.y);
            #pragma unroll
            for (int np = 0; np < 4; np++) {
                h2P[0][np] = fma2(ha[np], w00, h2P[0][np]);
                h2P[1][np] = fma2(ha[np], w01, h2P[1][np]);
                h2P[0][np] = fma2(hb[np], w10, h2P[0][np]);
                h2P[1][np] = fma2(hb[np], w11, h2P[1][np]);
            }
        }
        #pragma unroll
        for (int np = 0; np < 4; np++) {
            float a, b;
            upk2(h2P[0][np], a, b); F2 p0 = pk2(fmaxf(a, 0.0f), fmaxf(b, 0.0f));
            upk2(h2P[1][np], a, b); F2 p1 = pk2(fmaxf(a, 0.0f), fmaxf(b, 0.0f));
            ulonglong2 st; st.x = p0; st.y = p1;
            *(ulonglong2*)&h2S[np * 64 + 2 * l] = st;
        }
        __syncwarp();

        // --- heads: 64 -> 30 (lane owns output c = l, c<30; 30/31 compute zeros) ---
        F2 hdP[4];
        {
            float hb = sm[OFF_HB + l];
            #pragma unroll
            for (int np = 0; np < 4; np++) hdP[np] = dup2(hb);
        }
        #pragma unroll 2
        for (int jj = 0; jj < 32; jj++) {
            const int j = jj * 2;
            F2 ha[4], hb[4];
            #pragma unroll
            for (int np = 0; np < 4; np++) {
                ulonglong2 v = *(const ulonglong2*)&h2S[np * 64 + j];
                ha[np] = v.x; hb[np] = v.y;
            }
            F2 w0 = dup2(SHW[j * 32 + l]);
            F2 w1 = dup2(SHW[(j + 1) * 32 + l]);
            #pragma unroll
            for (int np = 0; np < 4; np++) {
                hdP[np] = fma2(ha[np], w0, hdP[np]);
                hdP[np] = fma2(hb[np], w1, hdP[np]);
            }
        }
        #pragma unroll
        for (int np = 0; np < 4; np++) hdS[np * 32 + l] = hdP[np];
        __syncwarp();

        // ===== mixture log-density for seq n_lane =====
        {
            const int off = np_l * 64 + pe;   // float index base into hdf
            float ck[10], ak[10];
            float cmax = -1e30f, amax = -1e30f;
            #pragma unroll
            for (int k = 0; k < 10; k++) {
                float mu = hdf[off + k * 2];
                float sg = hdf[off + (10 + k) * 2];
                float al = hdf[off + (20 + k) * 2];
                float z = (xt - mu) * __expf(-sg);
                float cc = fmaf(z, -0.5f * z, al - sg) - HALF_LOG2PI;
                ck[k] = cc; ak[k] = al;
                cmax = fmaxf(cmax, cc); amax = fmaxf(amax, al);
            }
            float sc = 0.0f, sa = 0.0f;
            #pragma unroll
            for (int k = 0; k < 10; k++) {
                sc += __expf(ck[k] - cmax);
                sa += __expf(ak[k] - amax);
            }
            res += (cmax + __logf(sc)) - (amax + __logf(sa));
        }

        xp = xt;
    }

    if (l < 8) out[n0 + l] = expf(res);
}

extern "C" void kernel_launch(void* const* d_in, const int* in_sizes, int n_in,
                              void* d_out, int out_size) {
    const float* x      = (const float*)d_in[0];
    const float* enc1_w = (const float*)d_in[1];
    const float* enc1_b = (const float*)d_in[2];
    const float* enc2_w = (const float*)d_in[3];
    const float* enc2_b = (const float*)d_in[4];
    const float* A      = (const float*)d_in[5];
    const float* init_w = (const float*)d_in[6];
    const float* n1w    = (const float*)d_in[7];
    const float* n1b    = (const float*)d_in[8];
    const float* n2w    = (const float*)d_in[9];
    const float* n2b    = (const float*)d_in[10];
    const float* mu_w   = (const float*)d_in[11];
    const float* mu_b   = (const float*)d_in[12];
    const float* sg_w   = (const float*)d_in[13];
    const float* sg_b   = (const float*)d_in[14];
    const float* al_w   = (const float*)d_in[15];
    const float* al_b   = (const float*)d_in[16];
    float* out = (float*)d_out;

    const int smem_bytes = SMEM_FLOATS * (int)sizeof(float);
    cudaFuncSetAttribute(wfa_kernel, cudaFuncAttributeMaxDynamicSharedMemorySize, smem_bytes);
    wfa_kernel<<<NBLOCKS, THREADS, smem_bytes>>>(
        x, enc1_w, enc1_b, enc2_w, enc2_b, A, init_w,
        n1w, n1b, n2w, n2b, mu_w, mu_b, sg_w, sg_b, al_w, al_b, out);
}

// round 4
// speedup vs baseline: 2.5623x; 1.0454x over previous
#include <cuda_runtime.h>
#include <math.h>

#define NSEQ 4096
#define T 128
#define THREADS 256
#define NBLOCKS 128
#define SEQ_PER_WARP 4

// ---- f32x2 packed helpers ----
typedef unsigned long long F2;

__device__ __forceinline__ F2 pk2(float lo, float hi) {
    F2 r; asm("mov.b64 %0,{%1,%2};" : "=l"(r) : "f"(lo), "f"(hi)); return r;
}
__device__ __forceinline__ void upk2(F2 v, float& lo, float& hi) {
    asm("mov.b64 {%0,%1},%2;" : "=f"(lo), "=f"(hi) : "l"(v));
}
__device__ __forceinline__ F2 fma2(F2 a, F2 b, F2 c) {
    F2 d; asm("fma.rn.f32x2 %0,%1,%2,%3;" : "=l"(d) : "l"(a), "l"(b), "l"(c)); return d;
}
__device__ __forceinline__ F2 dup2(float w) { return pk2(w, w); }

__device__ __forceinline__ float tanh_fast(float x) {
    float e = __expf(2.0f * x);
    return 1.0f - __fdividef(2.0f, e + 1.0f);
}

// ---- shared memory layout (float offsets) ----
#define OFF_A    0        // A[i][d][j]            8192
#define OFF_W1   8192     // nade1_w[i][o]         2048
#define OFF_W2   10240    // nade2_w[k][o]         4096
#define OFF_HW   14336    // HW[j][c] c:0..29 pad32  2048
#define OFF_E1W  16384    // 64
#define OFF_E1B  16448    // 64
#define OFF_E2T  16512    // Enc2T[d][i] 8x68      544
#define OFF_E2B  17056    // 8
#define OFF_B1   17064    // 64
#define OFF_B2   17128    // 64
#define OFF_INIT 17192    // 32
#define OFF_HB   17224    // 32
#define W_TOT    17256

// per-warp activation scratch (float offsets inside warp block), P=2 pairs
#define ACT_TMP  0        // F2 [np][32]   128 floats
#define ACT_TH   128      // F2 [np][32]   128
#define ACT_H1   256      // F2 [np][64]   256
#define ACT_H2   512      // F2 [np][64]   256
#define ACT_E    768      // F2 [np][8]    32
#define ACT_HD   800      // F2 [np][32]   128
#define WARP_ACT 960

#define NWARPS 8
#define SMEM_FLOATS (W_TOT + NWARPS * WARP_ACT)

__global__ void __launch_bounds__(THREADS, 1) wfa_kernel(
    const float* __restrict__ x,
    const float* __restrict__ enc1_w, const float* __restrict__ enc1_b,
    const float* __restrict__ enc2_w, const float* __restrict__ enc2_b,
    const float* __restrict__ A_g,
    const float* __restrict__ init_w,
    const float* __restrict__ n1w, const float* __restrict__ n1b,
    const float* __restrict__ n2w, const float* __restrict__ n2b,
    const float* __restrict__ mu_w, const float* __restrict__ mu_b,
    const float* __restrict__ sg_w, const float* __restrict__ sg_b,
    const float* __restrict__ al_w, const float* __restrict__ al_b,
    float* __restrict__ out)
{
    extern __shared__ float sm[];
    const int tid = threadIdx.x;

    // ---- stage weights ----
    for (int i = tid; i < 8192; i += THREADS) sm[OFF_A + i]  = A_g[i];
    for (int i = tid; i < 2048; i += THREADS) sm[OFF_W1 + i] = n1w[i];
    for (int i = tid; i < 4096; i += THREADS) sm[OFF_W2 + i] = n2w[i];
    for (int i = tid; i < 2048; i += THREADS) {
        int j = i >> 5, c = i & 31;
        float v = 0.0f;
        if (c < 10)      v = mu_w[j * 10 + c];
        else if (c < 20) v = sg_w[j * 10 + (c - 10)];
        else if (c < 30) v = al_w[j * 10 + (c - 20)];
        sm[OFF_HW + i] = v;
    }
    for (int i = tid; i < 544; i += THREADS) {
        int d = i / 68, ii = i % 68;
        sm[OFF_E2T + i] = (ii < 64) ? enc2_w[ii * 8 + d] : 0.0f;
    }
    if (tid < 64) {
        sm[OFF_E1W + tid] = enc1_w[tid];
        sm[OFF_E1B + tid] = enc1_b[tid];
        sm[OFF_B1 + tid]  = n1b[tid];
        sm[OFF_B2 + tid]  = n2b[tid];
    }
    if (tid < 8)  sm[OFF_E2B + tid]  = enc2_b[tid];
    if (tid < 32) sm[OFF_INIT + tid] = init_w[tid];
    if (tid < 32) {
        int c = tid; float v = 0.0f;
        if (c < 10)      v = mu_b[c];
        else if (c < 20) v = sg_b[c - 10];
        else if (c < 30) v = al_b[c - 20];
        sm[OFF_HB + c] = v;
    }
    __syncthreads();

    const int wid = tid >> 5;
    const int l   = tid & 31;
    const int n_lane = l & 3;          // seq index within warp (enc/mixture role)
    const int np_l   = n_lane >> 1;    // pair index
    const int pe     = n_lane & 1;     // element within pair
    const int d0     = l >> 2;         // encoder d slice 0..7
    const int kh     = (l >> 2) & 1;   // mixture k-half for lanes 0..7

    float* act = sm + W_TOT + wid * WARP_ACT;
    F2* tmpS  = (F2*)(act + ACT_TMP);   // [np*32 + j]
    F2* thS   = (F2*)(act + ACT_TH);    // [np*32 + i]
    F2* h1S   = (F2*)(act + ACT_H1);    // [np*64 + o]
    F2* h2S   = (F2*)(act + ACT_H2);    // [np*64 + o]
    F2* eS    = (F2*)(act + ACT_E);     // [np*8 + d]
    F2* hdS   = (F2*)(act + ACT_HD);    // [np*32 + c]
    float* eSf = (float*)eS;
    float* hdf = (float*)hdS;

    const float* SA  = sm + OFF_A;
    const float* SW1 = sm + OFF_W1;
    const float* SW2 = sm + OFF_W2;

    // ---- per-lane register caches ----
    float HWreg[64];                    // head weight column c=l (zeros for l>=30)
    #pragma unroll
    for (int j = 0; j < 64; j++) HWreg[j] = sm[OFF_HW + j * 32 + l];
    const F2 B1a = dup2(sm[OFF_B1 + 2 * l]);
    const F2 B1b = dup2(sm[OFF_B1 + 2 * l + 1]);
    const F2 B2a = dup2(sm[OFF_B2 + 2 * l]);
    const F2 B2b = dup2(sm[OFF_B2 + 2 * l + 1]);
    const F2 HBd = dup2(sm[OFF_HB + l]);
    const float e2b = sm[OFF_E2B + d0];

    const int n0 = blockIdx.x * 32 + wid * SEQ_PER_WARP;
    const float* xrow = x + (n0 + n_lane) * T;
    const float HALF_LOG2PI = 0.9189385332046727f;

    // ---- init state: lane owns j = l for 4 seqs (2 pairs) ----
    F2 tmpP[2];
    {
        float iv = sm[OFF_INIT + l];
        #pragma unroll
        for (int np = 0; np < 2; np++) { tmpP[np] = dup2(iv); tmpS[np * 32 + l] = tmpP[np]; }
    }
    __syncwarp();

    float res = 0.0f;
    float xp = 0.0f;

    #pragma unroll 1
    for (int t = 0; t < T; t++) {
        const float xt = __ldg(&xrow[t]);

        if (t > 0) {
            // ===== encoder: lane computes e[seq=n_lane][d=d0] =====
            float acc = 0.0f;
            const float* Et = sm + OFF_E2T + d0 * 68;
            #pragma unroll 4
            for (int i = 0; i < 64; i += 4) {
                float4 w  = *(const float4*)&sm[OFF_E1W + i];
                float4 b  = *(const float4*)&sm[OFF_E1B + i];
                float4 tv = *(const float4*)&Et[i];
                acc = fmaf(fmaxf(fmaf(xp, w.x, b.x), 0.0f), tv.x, acc);
                acc = fmaf(fmaxf(fmaf(xp, w.y, b.y), 0.0f), tv.y, acc);
                acc = fmaf(fmaxf(fmaf(xp, w.z, b.z), 0.0f), tv.z, acc);
                acc = fmaf(fmaxf(fmaf(xp, w.w, b.w), 0.0f), tv.w, acc);
            }
            const float ev = tanh_fast(acc + e2b);
            __syncwarp();
            eSf[(np_l * 8 + d0) * 2 + pe] = ev;
            __syncwarp();

            // ===== einsum: u[np][d] = sum_i tmp[np][i] * A[i][d][l] =====
            F2 u[16];
            #pragma unroll
            for (int q = 0; q < 16; q++) u[q] = 0ULL;
            #pragma unroll 4
            for (int ii = 0; ii < 16; ii++) {
                const int i = ii * 2;
                F2 tva[2], tvb[2];
                #pragma unroll
                for (int np = 0; np < 2; np++) {
                    ulonglong2 v = *(const ulonglong2*)&tmpS[np * 32 + i];
                    tva[np] = v.x; tvb[np] = v.y;
                }
                const float* Ar = SA + i * 256 + l;
                #pragma unroll
                for (int d = 0; d < 8; d++) {
                    F2 ap = dup2(Ar[d * 32]);
                    F2 bp = dup2(Ar[256 + d * 32]);
                    #pragma unroll
                    for (int np = 0; np < 2; np++) {
                        u[np * 8 + d] = fma2(tva[np], ap, u[np * 8 + d]);
                        u[np * 8 + d] = fma2(tvb[np], bp, u[np * 8 + d]);
                    }
                }
            }
            // combine: tmp_new[np] = sum_d e[np][d] * u[np][d]
            F2 nt[2] = {0ULL, 0ULL};
            #pragma unroll
            for (int d = 0; d < 8; d += 2) {
                #pragma unroll
                for (int np = 0; np < 2; np++) {
                    ulonglong2 evv = *(const ulonglong2*)&eS[np * 8 + d];
                    nt[np] = fma2(evv.x, u[np * 8 + d], nt[np]);
                    nt[np] = fma2(evv.y, u[np * 8 + d + 1], nt[np]);
                }
            }
            __syncwarp();   // all lanes done reading old tmpS
            tmpP[0] = nt[0]; tmpP[1] = nt[1];
        }

        // ===== phi =====
        // store state + tanh(state)
        #pragma unroll
        for (int np = 0; np < 2; np++) {
            float a, b; upk2(tmpP[np], a, b);
            tmpS[np * 32 + l] = tmpP[np];
            thS[np * 32 + l]  = pk2(tanh_fast(a), tanh_fast(b));
        }
        __syncwarp();

        // --- W1: 32 -> 64, lane owns o = 2l, 2l+1 ---
        F2 h1P[2][2] = {{B1a, B1a}, {B1b, B1b}};
        h1P[0][0] = B1a; h1P[0][1] = B1a; h1P[1][0] = B1b; h1P[1][1] = B1b;
        #pragma unroll 4
        for (int ii = 0; ii < 16; ii++) {
            const int i = ii * 2;
            F2 ta[2], tb[2];
            #pragma unroll
            for (int np = 0; np < 2; np++) {
                ulonglong2 v = *(const ulonglong2*)&thS[np * 32 + i];
                ta[np] = v.x; tb[np] = v.y;
            }
            float2 w0 = *(const float2*)&SW1[i * 64 + 2 * l];
            float2 w1 = *(const float2*)&SW1[(i + 1) * 64 + 2 * l];
            F2 w00 = dup2(w0.x), w01 = dup2(w0.y), w10 = dup2(w1.x), w11 = dup2(w1.y);
            #pragma unroll
            for (int np = 0; np < 2; np++) {
                h1P[0][np] = fma2(ta[np], w00, h1P[0][np]);
                h1P[1][np] = fma2(ta[np], w01, h1P[1][np]);
                h1P[0][np] = fma2(tb[np], w10, h1P[0][np]);
                h1P[1][np] = fma2(tb[np], w11, h1P[1][np]);
            }
        }
        #pragma unroll
        for (int np = 0; np < 2; np++) {
            float a, b;
            upk2(h1P[0][np], a, b); F2 p0 = pk2(fmaxf(a, 0.0f), fmaxf(b, 0.0f));
            upk2(h1P[1][np], a, b); F2 p1 = pk2(fmaxf(a, 0.0f), fmaxf(b, 0.0f));
            ulonglong2 st; st.x = p0; st.y = p1;
            *(ulonglong2*)&h1S[np * 64 + 2 * l] = st;
        }
        __syncwarp();

        // --- W2: 64 -> 64 ---
        F2 h2P[2][2];
        h2P[0][0] = B2a; h2P[0][1] = B2a; h2P[1][0] = B2b; h2P[1][1] = B2b;
        #pragma unroll 4
        for (int kk = 0; kk < 32; kk++) {
            const int k = kk * 2;
            F2 ha[2], hb[2];
            #pragma unroll
            for (int np = 0; np < 2; np++) {
                ulonglong2 v = *(const ulonglong2*)&h1S[np * 64 + k];
                ha[np] = v.x; hb[np] = v.y;
            }
            float2 w0 = *(const float2*)&SW2[k * 64 + 2 * l];
            float2 w1 = *(const float2*)&SW2[(k + 1) * 64 + 2 * l];
            F2 w00 = dup2(w0.x), w01 = dup2(w0.y), w10 = dup2(w1.x), w11 = dup2(w1.y);
            #pragma unroll
            for (int np = 0; np < 2; np++) {
                h2P[0][np] = fma2(ha[np], w00, h2P[0][np]);
                h2P[1][np] = fma2(ha[np], w01, h2P[1][np]);
                h2P[0][np] = fma2(hb[np], w10, h2P[0][np]);
                h2P[1][np] = fma2(hb[np], w11, h2P[1][np]);
            }
        }
        #pragma unroll
        for (int np = 0; np < 2; np++) {
            float a, b;
            upk2(h2P[0][np], a, b); F2 p0 = pk2(fmaxf(a, 0.0f), fmaxf(b, 0.0f));
            upk2(h2P[1][np], a, b); F2 p1 = pk2(fmaxf(a, 0.0f), fmaxf(b, 0.0f));
            ulonglong2 st; st.x = p0; st.y = p1;
            *(ulonglong2*)&h2S[np * 64 + 2 * l] = st;
        }
        __syncwarp();

        // --- heads: 64 -> 30, lane owns c = l (weights in registers) ---
        F2 hdP[2] = {HBd, HBd};
        #pragma unroll 4
        for (int jj = 0; jj < 32; jj++) {
            const int j = jj * 2;
            F2 w0 = dup2(HWreg[j]);
            F2 w1 = dup2(HWreg[j + 1]);
            #pragma unroll
            for (int np = 0; np < 2; np++) {
                ulonglong2 v = *(const ulonglong2*)&h2S[np * 64 + j];
                hdP[np] = fma2(v.x, w0, hdP[np]);
                hdP[np] = fma2(v.y, w1, hdP[np]);
            }
        }
        #pragma unroll
        for (int np = 0; np < 2; np++) hdS[np * 32 + l] = hdP[np];
        __syncwarp();

        // ===== mixture log-density: lanes 0..7, 2 lanes per seq, 5 comps each =====
        {
            const unsigned FULL = 0xffffffffu;
            const int off = np_l * 64 + pe;       // float base into hdf for this seq
            const int kb = kh * 5;
            float ck[5], ak[5];
            float cmax = -1e30f, amax = -1e30f;
            #pragma unroll
            for (int k = 0; k < 5; k++) {
                float mu = hdf[off + (kb + k) * 2];
                float sg = hdf[off + (10 + kb + k) * 2];
                float al = hdf[off + (20 + kb + k) * 2];
                float z = (xt - mu) * __expf(-sg);
                float cc = fmaf(z, -0.5f * z, al - sg) - HALF_LOG2PI;
                ck[k] = cc; ak[k] = al;
                cmax = fmaxf(cmax, cc); amax = fmaxf(amax, al);
            }
            cmax = fmaxf(cmax, __shfl_xor_sync(FULL, cmax, 4, 8));
            amax = fmaxf(amax, __shfl_xor_sync(FULL, amax, 4, 8));
            float sc = 0.0f, sa = 0.0f;
            #pragma unroll
            for (int k = 0; k < 5; k++) {
                sc += __expf(ck[k] - cmax);
                sa += __expf(ak[k] - amax);
            }
            sc += __shfl_xor_sync(FULL, sc, 4, 8);
            sa += __shfl_xor_sync(FULL, sa, 4, 8);
            res += (cmax + __logf(sc)) - (amax + __logf(sa));
        }

        xp = xt;
    }

    if (l < 4) out[n0 + l] = expf(res);
}

extern "C" void kernel_launch(void* const* d_in, const int* in_sizes, int n_in,
                              void* d_out, int out_size) {
    const float* x      = (const float*)d_in[0];
    const float* enc1_w = (const float*)d_in[1];
    const float* enc1_b = (const float*)d_in[2];
    const float* enc2_w = (const float*)d_in[3];
    const float* enc2_b = (const float*)d_in[4];
    const float* A      = (const float*)d_in[5];
    const float* init_w = (const float*)d_in[6];
    const float* n1w    = (const float*)d_in[7];
    const float* n1b    = (const float*)d_in[8];
    const float* n2w    = (const float*)d_in[9];
    const float* n2b    = (const float*)d_in[10];
    const float* mu_w   = (const float*)d_in[11];
    const float* mu_b   = (const float*)d_in[12];
    const float* sg_w   = (const float*)d_in[13];
    const float* sg_b   = (const float*)d_in[14];
    const float* al_w   = (const float*)d_in[15];
    const float* al_b   = (const float*)d_in[16];
    float* out = (float*)d_out;

    const int smem_bytes = SMEM_FLOATS * (int)sizeof(float);
    cudaFuncSetAttribute(wfa_kernel, cudaFuncAttributeMaxDynamicSharedMemorySize, smem_bytes);
    wfa_kernel<<<NBLOCKS, THREADS, smem_bytes>>>(
        x, enc1_w, enc1_b, enc2_w, enc2_b, A, init_w,
        n1w, n1b, n2w, n2b, mu_w, mu_b, sg_w, sg_b, al_w, al_b, out);
}

// round 5
// speedup vs baseline: 3.1461x; 1.2278x over previous
#include <cuda_runtime.h>
#include <math.h>

#define NSEQ 4096
#define T 128
#define THREADS 256
#define NBLOCKS 128
#define SEQ_PER_WARP 4

// ---- f32x2 packed helpers ----
typedef unsigned long long F2;

__device__ __forceinline__ F2 pk2(float lo, float hi) {
    F2 r; asm("mov.b64 %0,{%1,%2};" : "=l"(r) : "f"(lo), "f"(hi)); return r;
}
__device__ __forceinline__ void upk2(F2 v, float& lo, float& hi) {
    asm("mov.b64 {%0,%1},%2;" : "=f"(lo), "=f"(hi) : "l"(v));
}
__device__ __forceinline__ F2 fma2(F2 a, F2 b, F2 c) {
    F2 d; asm("fma.rn.f32x2 %0,%1,%2,%3;" : "=l"(d) : "l"(a), "l"(b), "l"(c)); return d;
}
__device__ __forceinline__ F2 dup2(float w) { return pk2(w, w); }

__device__ __forceinline__ float tanh_fast(float x) {
    float e = __expf(2.0f * x);
    return 1.0f - __fdividef(2.0f, e + 1.0f);
}

// ---- shared memory layout (float offsets) ----
#define OFF_A    0        // A[i][d][j]            8192
#define OFF_W1   8192     // nade1_w[i][o]         2048
#define OFF_W2   10240    // nade2_w[k][o]         4096
#define OFF_HW   14336    // HW[j][c] c:0..29 pad32  2048
#define OFF_E1W  16384    // 64
#define OFF_E1B  16448    // 64
#define OFF_E2T  16512    // Enc2T[d][i] 8x68      544
#define OFF_E2B  17056    // 8
#define OFF_B1   17064    // 64
#define OFF_B2   17128    // 64
#define OFF_INIT 17192    // 32
#define OFF_HB   17224    // 32
#define W_TOT    17256

// per-warp activation scratch (float offsets inside warp block)
// 8 q-pairs per phi pass (4 steps x 2 seq-pairs)
#define ACT_TMP  0        // F2 [np][32]      128 floats
#define ACT_TH   128      // F2 [q8][32]      512
#define ACT_H1   640      // F2 [q8][64]      1024
#define ACT_H2   1664     // F2 [q8][64]      1024
#define ACT_E    2688     // F2 [np][8]       32
#define ACT_HD   2720     // F2 [q8][32]      512
#define ACT_X    3232     // float [5][4]     20 (pad 32)
#define WARP_ACT 3264

#define NWARPS 8
#define SMEM_FLOATS (W_TOT + NWARPS * WARP_ACT)

__global__ void __launch_bounds__(THREADS, 1) wfa_kernel(
    const float* __restrict__ x,
    const float* __restrict__ enc1_w, const float* __restrict__ enc1_b,
    const float* __restrict__ enc2_w, const float* __restrict__ enc2_b,
    const float* __restrict__ A_g,
    const float* __restrict__ init_w,
    const float* __restrict__ n1w, const float* __restrict__ n1b,
    const float* __restrict__ n2w, const float* __restrict__ n2b,
    const float* __restrict__ mu_w, const float* __restrict__ mu_b,
    const float* __restrict__ sg_w, const float* __restrict__ sg_b,
    const float* __restrict__ al_w, const float* __restrict__ al_b,
    float* __restrict__ out)
{
    extern __shared__ float sm[];
    const int tid = threadIdx.x;

    // ---- stage weights ----
    for (int i = tid; i < 8192; i += THREADS) sm[OFF_A + i]  = A_g[i];
    for (int i = tid; i < 2048; i += THREADS) sm[OFF_W1 + i] = n1w[i];
    for (int i = tid; i < 4096; i += THREADS) sm[OFF_W2 + i] = n2w[i];
    for (int i = tid; i < 2048; i += THREADS) {
        int j = i >> 5, c = i & 31;
        float v = 0.0f;
        if (c < 10)      v = mu_w[j * 10 + c];
        else if (c < 20) v = sg_w[j * 10 + (c - 10)];
        else if (c < 30) v = al_w[j * 10 + (c - 20)];
        sm[OFF_HW + i] = v;
    }
    for (int i = tid; i < 544; i += THREADS) {
        int d = i / 68, ii = i % 68;
        sm[OFF_E2T + i] = (ii < 64) ? enc2_w[ii * 8 + d] : 0.0f;
    }
    if (tid < 64) {
        sm[OFF_E1W + tid] = enc1_w[tid];
        sm[OFF_E1B + tid] = enc1_b[tid];
        sm[OFF_B1 + tid]  = n1b[tid];
        sm[OFF_B2 + tid]  = n2b[tid];
    }
    if (tid < 8)  sm[OFF_E2B + tid]  = enc2_b[tid];
    if (tid < 32) sm[OFF_INIT + tid] = init_w[tid];
    if (tid < 32) {
        int c = tid; float v = 0.0f;
        if (c < 10)      v = mu_b[c];
        else if (c < 20) v = sg_b[c - 10];
        else if (c < 30) v = al_b[c - 20];
        sm[OFF_HB + c] = v;
    }
    __syncthreads();

    const unsigned FULL = 0xffffffffu;
    const int wid = tid >> 5;
    const int l   = tid & 31;
    const int n_lane = l & 3;          // seq index within warp (x load / encoder role)
    const int np_l   = n_lane >> 1;    // pair index
    const int pe     = n_lane & 1;     // element within pair
    const int d0     = l >> 2;         // encoder d slice 0..7

    float* act = sm + W_TOT + wid * WARP_ACT;
    F2* tmpS  = (F2*)(act + ACT_TMP);   // [np*32 + j]
    F2* thS   = (F2*)(act + ACT_TH);    // [q*32 + i]
    F2* h1S   = (F2*)(act + ACT_H1);    // [q*64 + o]
    F2* h2S   = (F2*)(act + ACT_H2);    // [q*64 + o]
    F2* eS    = (F2*)(act + ACT_E);     // [np*8 + d]
    F2* hdS   = (F2*)(act + ACT_HD);    // [q*32 + c]
    float* eSf = (float*)eS;
    float* hdf = (float*)hdS;
    float* xSf = act + ACT_X;           // [step+1][seq]

    const float* SA  = sm + OFF_A;
    const float* SW1 = sm + OFF_W1;
    const float* SW2 = sm + OFF_W2;

    // ---- per-lane register caches ----
    float HWreg[64];                    // head weight column c=l (zeros for l>=30)
    #pragma unroll
    for (int j = 0; j < 64; j++) HWreg[j] = sm[OFF_HW + j * 32 + l];
    const F2 B1a = dup2(sm[OFF_B1 + 2 * l]);
    const F2 B1b = dup2(sm[OFF_B1 + 2 * l + 1]);
    const F2 B2a = dup2(sm[OFF_B2 + 2 * l]);
    const F2 B2b = dup2(sm[OFF_B2 + 2 * l + 1]);
    const F2 HBd = dup2(sm[OFF_HB + l]);
    const float e2b = sm[OFF_E2B + d0];

    const int n0 = blockIdx.x * 32 + wid * SEQ_PER_WARP;
    const float* xrow = x + (n0 + n_lane) * T;
    const float HALF_LOG2PI = 0.9189385332046727f;

    // mixture role: lane handles row r = l>>1 (16 rows = 4 steps x 4 seqs), kh = l&1
    const int r_m    = l >> 1;
    const int kh_m   = l & 1;
    const int step_m = r_m >> 2;
    const int sr_m   = r_m & 3;
    const int q_m    = step_m * 2 + (sr_m >> 1);
    const int pe_m   = sr_m & 1;
    const int kb_m   = kh_m * 5;
    const int hd_base = q_m * 64 + pe_m;

    // ---- init state: lane owns j = l for 4 seqs (2 pairs) ----
    F2 tmpP[2];
    {
        float iv = sm[OFF_INIT + l];
        #pragma unroll
        for (int np = 0; np < 2; np++) { tmpP[np] = dup2(iv); tmpS[np * 32 + l] = tmpP[np]; }
    }
    __syncwarp();

    float res = 0.0f;
    float xp = 0.0f;

    #pragma unroll 1
    for (int it = 0; it < 32; it++) {
        // ===== 4 sequential micro-steps: x load, encoder, einsum, tanh =====
        #pragma unroll 1
        for (int s = 0; s < 4; s++) {
            const int t = it * 4 + s;
            const float xt = __ldg(&xrow[t]);
            if (l < 4) xSf[(s + 1) * 4 + l] = xt;

            if (t > 0) {
                // encoder: lane computes e[seq=n_lane][d=d0] from x_{t-1} (reg xp)
                float acc = 0.0f;
                const float* Et = sm + OFF_E2T + d0 * 68;
                #pragma unroll 4
                for (int i = 0; i < 64; i += 4) {
                    float4 w  = *(const float4*)&sm[OFF_E1W + i];
                    float4 b  = *(const float4*)&sm[OFF_E1B + i];
                    float4 tv = *(const float4*)&Et[i];
                    acc = fmaf(fmaxf(fmaf(xp, w.x, b.x), 0.0f), tv.x, acc);
                    acc = fmaf(fmaxf(fmaf(xp, w.y, b.y), 0.0f), tv.y, acc);
                    acc = fmaf(fmaxf(fmaf(xp, w.z, b.z), 0.0f), tv.z, acc);
                    acc = fmaf(fmaxf(fmaf(xp, w.w, b.w), 0.0f), tv.w, acc);
                }
                const float ev = tanh_fast(acc + e2b);
                __syncwarp();
                eSf[(np_l * 8 + d0) * 2 + pe] = ev;
                __syncwarp();

                // einsum: u[np][d] = sum_i tmp[np][i] * A[i][d][l]
                F2 u[16];
                #pragma unroll
                for (int q = 0; q < 16; q++) u[q] = 0ULL;
                #pragma unroll 4
                for (int ii = 0; ii < 16; ii++) {
                    const int i = ii * 2;
                    F2 tva[2], tvb[2];
                    #pragma unroll
                    for (int np = 0; np < 2; np++) {
                        ulonglong2 v = *(const ulonglong2*)&tmpS[np * 32 + i];
                        tva[np] = v.x; tvb[np] = v.y;
                    }
                    const float* Ar = SA + i * 256 + l;
                    #pragma unroll
                    for (int d = 0; d < 8; d++) {
                        F2 ap = dup2(Ar[d * 32]);
                        F2 bp = dup2(Ar[256 + d * 32]);
                        #pragma unroll
                        for (int np = 0; np < 2; np++) {
                            u[np * 8 + d] = fma2(tva[np], ap, u[np * 8 + d]);
                            u[np * 8 + d] = fma2(tvb[np], bp, u[np * 8 + d]);
                        }
                    }
                }
                F2 nt[2] = {0ULL, 0ULL};
                #pragma unroll
                for (int d = 0; d < 8; d += 2) {
                    #pragma unroll
                    for (int np = 0; np < 2; np++) {
                        ulonglong2 evv = *(const ulonglong2*)&eS[np * 8 + d];
                        nt[np] = fma2(evv.x, u[np * 8 + d], nt[np]);
                        nt[np] = fma2(evv.y, u[np * 8 + d + 1], nt[np]);
                    }
                }
                __syncwarp();   // all lanes done reading old tmpS
                tmpP[0] = nt[0]; tmpP[1] = nt[1];
            }

            // store state + tanh(state) into this step's th slot (q = s*2+np)
            #pragma unroll
            for (int np = 0; np < 2; np++) {
                float a, b; upk2(tmpP[np], a, b);
                tmpS[np * 32 + l] = tmpP[np];
                thS[(s * 2 + np) * 32 + l] = pk2(tanh_fast(a), tanh_fast(b));
            }
            xp = xt;
            __syncwarp();
        }

        // ===== phi batched over 16 rows (8 q-pairs) =====
        // --- W1: 32 -> 64, lane owns o = 2l, 2l+1 ---
        {
            F2 hA[8], hB[8];
            #pragma unroll
            for (int q = 0; q < 8; q++) { hA[q] = B1a; hB[q] = B1b; }
            #pragma unroll 2
            for (int ii = 0; ii < 16; ii++) {
                const int i = ii * 2;
                float2 w0 = *(const float2*)&SW1[i * 64 + 2 * l];
                float2 w1 = *(const float2*)&SW1[(i + 1) * 64 + 2 * l];
                F2 w00 = dup2(w0.x), w01 = dup2(w0.y), w10 = dup2(w1.x), w11 = dup2(w1.y);
                #pragma unroll
                for (int q = 0; q < 8; q++) {
                    ulonglong2 v = *(const ulonglong2*)&thS[q * 32 + i];
                    hA[q] = fma2(v.x, w00, hA[q]);
                    hB[q] = fma2(v.x, w01, hB[q]);
                    hA[q] = fma2(v.y, w10, hA[q]);
                    hB[q] = fma2(v.y, w11, hB[q]);
                }
            }
            #pragma unroll
            for (int q = 0; q < 8; q++) {
                float a, b;
                upk2(hA[q], a, b); F2 p0 = pk2(fmaxf(a, 0.0f), fmaxf(b, 0.0f));
                upk2(hB[q], a, b); F2 p1 = pk2(fmaxf(a, 0.0f), fmaxf(b, 0.0f));
                ulonglong2 st; st.x = p0; st.y = p1;
                *(ulonglong2*)&h1S[q * 64 + 2 * l] = st;
            }
        }
        __syncwarp();

        // --- W2: 64 -> 64 ---
        {
            F2 hA[8], hB[8];
            #pragma unroll
            for (int q = 0; q < 8; q++) { hA[q] = B2a; hB[q] = B2b; }
            #pragma unroll 2
            for (int kk = 0; kk < 32; kk++) {
                const int k = kk * 2;
                float2 w0 = *(const float2*)&SW2[k * 64 + 2 * l];
                float2 w1 = *(const float2*)&SW2[(k + 1) * 64 + 2 * l];
                F2 w00 = dup2(w0.x), w01 = dup2(w0.y), w10 = dup2(w1.x), w11 = dup2(w1.y);
                #pragma unroll
                for (int q = 0; q < 8; q++) {
                    ulonglong2 v = *(const ulonglong2*)&h1S[q * 64 + k];
                    hA[q] = fma2(v.x, w00, hA[q]);
                    hB[q] = fma2(v.x, w01, hB[q]);
                    hA[q] = fma2(v.y, w10, hA[q]);
                    hB[q] = fma2(v.y, w11, hB[q]);
                }
            }
            #pragma unroll
            for (int q = 0; q < 8; q++) {
                float a, b;
                upk2(hA[q], a, b); F2 p0 = pk2(fmaxf(a, 0.0f), fmaxf(b, 0.0f));
                upk2(hB[q], a, b); F2 p1 = pk2(fmaxf(a, 0.0f), fmaxf(b, 0.0f));
                ulonglong2 st; st.x = p0; st.y = p1;
                *(ulonglong2*)&h2S[q * 64 + 2 * l] = st;
            }
        }
        __syncwarp();

        // --- heads: 64 -> 30, lane owns c = l (weights in registers) ---
        {
            F2 hd[8];
            #pragma unroll
            for (int q = 0; q < 8; q++) hd[q] = HBd;
            #pragma unroll 2
            for (int jj = 0; jj < 32; jj++) {
                const int j = jj * 2;
                F2 w0 = dup2(HWreg[j]);
                F2 w1 = dup2(HWreg[j + 1]);
                #pragma unroll
                for (int q = 0; q < 8; q++) {
                    ulonglong2 v = *(const ulonglong2*)&h2S[q * 64 + j];
                    hd[q] = fma2(v.x, w0, hd[q]);
                    hd[q] = fma2(v.y, w1, hd[q]);
                }
            }
            #pragma unroll
            for (int q = 0; q < 8; q++) hdS[q * 32 + l] = hd[q];
        }
        __syncwarp();

        // ===== mixture: 32 lanes, 2 lanes per row, 5 comps each =====
        {
            const float xt_m = xSf[(step_m + 1) * 4 + sr_m];
            float ck[5], ak[5];
            float cmax = -1e30f, amax = -1e30f;
            #pragma unroll
            for (int k = 0; k < 5; k++) {
                float mu = hdf[hd_base + (kb_m + k) * 2];
                float sg = hdf[hd_base + (10 + kb_m + k) * 2];
                float al = hdf[hd_base + (20 + kb_m + k) * 2];
                float z = (xt_m - mu) * __expf(-sg);
                float cc = fmaf(z, -0.5f * z, al - sg) - HALF_LOG2PI;
                ck[k] = cc; ak[k] = al;
                cmax = fmaxf(cmax, cc); amax = fmaxf(amax, al);
            }
            cmax = fmaxf(cmax, __shfl_xor_sync(FULL, cmax, 1));
            amax = fmaxf(amax, __shfl_xor_sync(FULL, amax, 1));
            float sc = 0.0f, sa = 0.0f;
            #pragma unroll
            for (int k = 0; k < 5; k++) {
                sc += __expf(ck[k] - cmax);
                sa += __expf(ak[k] - amax);
            }
            sc += __shfl_xor_sync(FULL, sc, 1);
            sa += __shfl_xor_sync(FULL, sa, 1);
            res += (cmax + __logf(sc)) - (amax + __logf(sa));
        }
        __syncwarp();
    }

    // final reduce over the 4 step-slots (lanes l, l^8, l^16, l^24 share a seq)
    res += __shfl_xor_sync(FULL, res, 8);
    res += __shfl_xor_sync(FULL, res, 16);
    if (l < 8 && (l & 1) == 0) out[n0 + (l >> 1)] = expf(res);
}

extern "C" void kernel_launch(void* const* d_in, const int* in_sizes, int n_in,
                              void* d_out, int out_size) {
    const float* x      = (const float*)d_in[0];
    const float* enc1_w = (const float*)d_in[1];
    const float* enc1_b = (const float*)d_in[2];
    const float* enc2_w = (const float*)d_in[3];
    const float* enc2_b = (const float*)d_in[4];
    const float* A      = (const float*)d_in[5];
    const float* init_w = (const float*)d_in[6];
    const float* n1w    = (const float*)d_in[7];
    const float* n1b    = (const float*)d_in[8];
    const float* n2w    = (const float*)d_in[9];
    const float* n2b    = (const float*)d_in[10];
    const float* mu_w   = (const float*)d_in[11];
    const float* mu_b   = (const float*)d_in[12];
    const float* sg_w   = (const float*)d_in[13];
    const float* sg_b   = (const float*)d_in[14];
    const float* al_w   = (const float*)d_in[15];
    const float* al_b   = (const float*)d_in[16];
    float* out = (float*)d_out;

    const int smem_bytes = SMEM_FLOATS * (int)sizeof(float);
    cudaFuncSetAttribute(wfa_kernel, cudaFuncAttributeMaxDynamicSharedMemorySize, smem_bytes);
    wfa_kernel<<<NBLOCKS, THREADS, smem_bytes>>>(
        x, enc1_w, enc1_b, enc2_w, enc2_b, A, init_w,
        n1w, n1b, n2w, n2b, mu_w, mu_b, sg_w, sg_b, al_w, al_b, out);
}

// round 6
// speedup vs baseline: 3.1470x; 1.0003x over previous
#include <cuda_runtime.h>
#include <math.h>

#define NSEQ 4096
#define T 128
#define THREADS 256
#define NBLOCKS 128
#define SEQ_PER_WARP 4

// ---- f32x2 packed helpers ----
typedef unsigned long long F2;

__device__ __forceinline__ F2 pk2(float lo, float hi) {
    F2 r; asm("mov.b64 %0,{%1,%2};" : "=l"(r) : "f"(lo), "f"(hi)); return r;
}
__device__ __forceinline__ void upk2(F2 v, float& lo, float& hi) {
    asm("mov.b64 {%0,%1},%2;" : "=f"(lo), "=f"(hi) : "l"(v));
}
__device__ __forceinline__ F2 fma2(F2 a, F2 b, F2 c) {
    F2 d; asm("fma.rn.f32x2 %0,%1,%2,%3;" : "=l"(d) : "l"(a), "l"(b), "l"(c)); return d;
}
__device__ __forceinline__ F2 dup2(float w) { return pk2(w, w); }

__device__ __forceinline__ float tanh_fast(float x) {
    float e = __expf(2.0f * x);
    return 1.0f - __fdividef(2.0f, e + 1.0f);
}

// ---- shared memory layout (float offsets) ----
#define OFF_A    0        // A[i][d][j]            8192
#define OFF_W1   8192     // nade1_w[i][o]         2048
#define OFF_W2   10240    // nade2_w[k][o]         4096
#define OFF_HW   14336    // HW[j][c] c:0..29 pad32  2048
#define OFF_E1W  16384    // 64
#define OFF_E1B  16448    // 64
#define OFF_E2T  16512    // Enc2T[d][i] 8x68      544
#define OFF_E2B  17056    // 8
#define OFF_B1   17064    // 64
#define OFF_B2   17128    // 64
#define OFF_INIT 17192    // 32
#define OFF_HB   17224    // 32
#define W_TOT    17256

// per-warp activation scratch (float offsets inside warp block)
// 8 q-pairs per phi pass (4 steps x 2 seq-pairs)
#define ACT_TMP  0        // F2 [np][32]      128 floats
#define ACT_TH   128      // F2 [q8][32]      512
#define ACT_H1   640      // F2 [q8][64]      1024
#define ACT_H2   1664     // F2 [q8][64]      1024
#define ACT_E    2688     // F2 [np][8]       32
#define ACT_HD   2720     // F2 [q8][32]      512
#define ACT_X    3232     // float [5][4]     20 (pad 32)
#define WARP_ACT 3264

#define NWARPS 8
#define SMEM_FLOATS (W_TOT + NWARPS * WARP_ACT)

__global__ void __launch_bounds__(THREADS, 1) wfa_kernel(
    const float* __restrict__ x,
    const float* __restrict__ enc1_w, const float* __restrict__ enc1_b,
    const float* __restrict__ enc2_w, const float* __restrict__ enc2_b,
    const float* __restrict__ A_g,
    const float* __restrict__ init_w,
    const float* __restrict__ n1w, const float* __restrict__ n1b,
    const float* __restrict__ n2w, const float* __restrict__ n2b,
    const float* __restrict__ mu_w, const float* __restrict__ mu_b,
    const float* __restrict__ sg_w, const float* __restrict__ sg_b,
    const float* __restrict__ al_w, const float* __restrict__ al_b,
    float* __restrict__ out)
{
    extern __shared__ float sm[];
    const int tid = threadIdx.x;

    // ---- stage weights ----
    for (int i = tid; i < 8192; i += THREADS) sm[OFF_A + i]  = A_g[i];
    for (int i = tid; i < 2048; i += THREADS) sm[OFF_W1 + i] = n1w[i];
    for (int i = tid; i < 4096; i += THREADS) sm[OFF_W2 + i] = n2w[i];
    for (int i = tid; i < 2048; i += THREADS) {
        int j = i >> 5, c = i & 31;
        float v = 0.0f;
        if (c < 10)      v = mu_w[j * 10 + c];
        else if (c < 20) v = sg_w[j * 10 + (c - 10)];
        else if (c < 30) v = al_w[j * 10 + (c - 20)];
        sm[OFF_HW + i] = v;
    }
    for (int i = tid; i < 544; i += THREADS) {
        int d = i / 68, ii = i % 68;
        sm[OFF_E2T + i] = (ii < 64) ? enc2_w[ii * 8 + d] : 0.0f;
    }
    if (tid < 64) {
        sm[OFF_E1W + tid] = enc1_w[tid];
        sm[OFF_E1B + tid] = enc1_b[tid];
        sm[OFF_B1 + tid]  = n1b[tid];
        sm[OFF_B2 + tid]  = n2b[tid];
    }
    if (tid < 8)  sm[OFF_E2B + tid]  = enc2_b[tid];
    if (tid < 32) sm[OFF_INIT + tid] = init_w[tid];
    if (tid < 32) {
        int c = tid; float v = 0.0f;
        if (c < 10)      v = mu_b[c];
        else if (c < 20) v = sg_b[c - 10];
        else if (c < 30) v = al_b[c - 20];
        sm[OFF_HB + c] = v;
    }
    __syncthreads();

    const unsigned FULL = 0xffffffffu;
    const int wid = tid >> 5;
    const int l   = tid & 31;
    const int n_lane = l & 3;          // seq index within warp (x load / encoder role)
    const int np_l   = n_lane >> 1;    // pair index
    const int pe     = n_lane & 1;     // element within pair
    const int d0     = l >> 2;         // encoder d slice 0..7

    float* act = sm + W_TOT + wid * WARP_ACT;
    F2* tmpS  = (F2*)(act + ACT_TMP);   // [np*32 + j]
    F2* thS   = (F2*)(act + ACT_TH);    // [q*32 + i]
    F2* h1S   = (F2*)(act + ACT_H1);    // [q*64 + o]
    F2* h2S   = (F2*)(act + ACT_H2);    // [q*64 + o]
    F2* eS    = (F2*)(act + ACT_E);     // [np*8 + d]
    F2* hdS   = (F2*)(act + ACT_HD);    // [q*32 + c]
    float* eSf = (float*)eS;
    float* hdf = (float*)hdS;
    float* xSf = act + ACT_X;           // [step+1][seq]

    const float* SA  = sm + OFF_A;
    const float* SW1 = sm + OFF_W1;
    const float* SW2 = sm + OFF_W2;

    // ---- per-lane register caches ----
    float HWreg[64];                    // head weight column c=l (zeros for l>=30)
    #pragma unroll
    for (int j = 0; j < 64; j++) HWreg[j] = sm[OFF_HW + j * 32 + l];
    const F2 B1a = dup2(sm[OFF_B1 + 2 * l]);
    const F2 B1b = dup2(sm[OFF_B1 + 2 * l + 1]);
    const F2 B2a = dup2(sm[OFF_B2 + 2 * l]);
    const F2 B2b = dup2(sm[OFF_B2 + 2 * l + 1]);
    const F2 HBd = dup2(sm[OFF_HB + l]);
    const float e2b = sm[OFF_E2B + d0];

    const int n0 = blockIdx.x * 32 + wid * SEQ_PER_WARP;
    const float* xrow = x + (n0 + n_lane) * T;
    const float HALF_LOG2PI = 0.9189385332046727f;

    // mixture role: lane handles row r = l>>1 (16 rows = 4 steps x 4 seqs), kh = l&1
    const int r_m    = l >> 1;
    const int kh_m   = l & 1;
    const int step_m = r_m >> 2;
    const int sr_m   = r_m & 3;
    const int q_m    = step_m * 2 + (sr_m >> 1);
    const int pe_m   = sr_m & 1;
    const int kb_m   = kh_m * 5;
    const int hd_base = q_m * 64 + pe_m;

    // ---- init state: lane owns j = l for 4 seqs (2 pairs) ----
    F2 tmpP[2];
    {
        float iv = sm[OFF_INIT + l];
        #pragma unroll
        for (int np = 0; np < 2; np++) { tmpP[np] = dup2(iv); tmpS[np * 32 + l] = tmpP[np]; }
    }
    __syncwarp();

    float res = 0.0f;
    float xp = 0.0f;

    #pragma unroll 1
    for (int it = 0; it < 32; it++) {
        // ===== 4 sequential micro-steps: x load, encoder, einsum, tanh =====
        #pragma unroll 1
        for (int s = 0; s < 4; s++) {
            const int t = it * 4 + s;
            const float xt = __ldg(&xrow[t]);
            if (l < 4) xSf[(s + 1) * 4 + l] = xt;

            if (t > 0) {
                // encoder: lane computes e[seq=n_lane][d=d0] from x_{t-1} (reg xp)
                float acc = 0.0f;
                const float* Et = sm + OFF_E2T + d0 * 68;
                #pragma unroll 4
                for (int i = 0; i < 64; i += 4) {
                    float4 w  = *(const float4*)&sm[OFF_E1W + i];
                    float4 b  = *(const float4*)&sm[OFF_E1B + i];
                    float4 tv = *(const float4*)&Et[i];
                    acc = fmaf(fmaxf(fmaf(xp, w.x, b.x), 0.0f), tv.x, acc);
                    acc = fmaf(fmaxf(fmaf(xp, w.y, b.y), 0.0f), tv.y, acc);
                    acc = fmaf(fmaxf(fmaf(xp, w.z, b.z), 0.0f), tv.z, acc);
                    acc = fmaf(fmaxf(fmaf(xp, w.w, b.w), 0.0f), tv.w, acc);
                }
                const float ev = tanh_fast(acc + e2b);
                __syncwarp();
                eSf[(np_l * 8 + d0) * 2 + pe] = ev;
                __syncwarp();

                // einsum: u[np][d] = sum_i tmp[np][i] * A[i][d][l]
                F2 u[16];
                #pragma unroll
                for (int q = 0; q < 16; q++) u[q] = 0ULL;
                #pragma unroll 4
                for (int ii = 0; ii < 16; ii++) {
                    const int i = ii * 2;
                    F2 tva[2], tvb[2];
                    #pragma unroll
                    for (int np = 0; np < 2; np++) {
                        ulonglong2 v = *(const ulonglong2*)&tmpS[np * 32 + i];
                        tva[np] = v.x; tvb[np] = v.y;
                    }
                    const float* Ar = SA + i * 256 + l;
                    #pragma unroll
                    for (int d = 0; d < 8; d++) {
                        F2 ap = dup2(Ar[d * 32]);
                        F2 bp = dup2(Ar[256 + d * 32]);
                        #pragma unroll
                        for (int np = 0; np < 2; np++) {
                            u[np * 8 + d] = fma2(tva[np], ap, u[np * 8 + d]);
                            u[np * 8 + d] = fma2(tvb[np], bp, u[np * 8 + d]);
                        }
                    }
                }
                F2 nt[2] = {0ULL, 0ULL};
                #pragma unroll
                for (int d = 0; d < 8; d += 2) {
                    #pragma unroll
                    for (int np = 0; np < 2; np++) {
                        ulonglong2 evv = *(const ulonglong2*)&eS[np * 8 + d];
                        nt[np] = fma2(evv.x, u[np * 8 + d], nt[np]);
                        nt[np] = fma2(evv.y, u[np * 8 + d + 1], nt[np]);
                    }
                }
                __syncwarp();   // all lanes done reading old tmpS
                tmpP[0] = nt[0]; tmpP[1] = nt[1];
            }

            // store state + tanh(state) into this step's th slot (q = s*2+np)
            #pragma unroll
            for (int np = 0; np < 2; np++) {
                float a, b; upk2(tmpP[np], a, b);
                tmpS[np * 32 + l] = tmpP[np];
                thS[(s * 2 + np) * 32 + l] = pk2(tanh_fast(a), tanh_fast(b));
            }
            xp = xt;
            __syncwarp();
        }

        // ===== phi batched over 16 rows (8 q-pairs) =====
        // --- W1: 32 -> 64, lane owns o = 2l, 2l+1 ---
        {
            F2 hA[8], hB[8];
            #pragma unroll
            for (int q = 0; q < 8; q++) { hA[q] = B1a; hB[q] = B1b; }
            #pragma unroll 2
            for (int ii = 0; ii < 16; ii++) {
                const int i = ii * 2;
                float2 w0 = *(const float2*)&SW1[i * 64 + 2 * l];
                float2 w1 = *(const float2*)&SW1[(i + 1) * 64 + 2 * l];
                F2 w00 = dup2(w0.x), w01 = dup2(w0.y), w10 = dup2(w1.x), w11 = dup2(w1.y);
                #pragma unroll
                for (int q = 0; q < 8; q++) {
                    ulonglong2 v = *(const ulonglong2*)&thS[q * 32 + i];
                    hA[q] = fma2(v.x, w00, hA[q]);
                    hB[q] = fma2(v.x, w01, hB[q]);
                    hA[q] = fma2(v.y, w10, hA[q]);
                    hB[q] = fma2(v.y, w11, hB[q]);
                }
            }
            #pragma unroll
            for (int q = 0; q < 8; q++) {
                float a, b;
                upk2(hA[q], a, b); F2 p0 = pk2(fmaxf(a, 0.0f), fmaxf(b, 0.0f));
                upk2(hB[q], a, b); F2 p1 = pk2(fmaxf(a, 0.0f), fmaxf(b, 0.0f));
                ulonglong2 st; st.x = p0; st.y = p1;
                *(ulonglong2*)&h1S[q * 64 + 2 * l] = st;
            }
        }
        __syncwarp();

        // --- W2: 64 -> 64 ---
        {
            F2 hA[8], hB[8];
            #pragma unroll
            for (int q = 0; q < 8; q++) { hA[q] = B2a; hB[q] = B2b; }
            #pragma unroll 2
            for (int kk = 0; kk < 32; kk++) {
                const int k = kk * 2;
                float2 w0 = *(const float2*)&SW2[k * 64 + 2 * l];
                float2 w1 = *(const float2*)&SW2[(k + 1) * 64 + 2 * l];
                F2 w00 = dup2(w0.x), w01 = dup2(w0.y), w10 = dup2(w1.x), w11 = dup2(w1.y);
                #pragma unroll
                for (int q = 0; q < 8; q++) {
                    ulonglong2 v = *(const ulonglong2*)&h1S[q * 64 + k];
                    hA[q] = fma2(v.x, w00, hA[q]);
                    hB[q] = fma2(v.x, w01, hB[q]);
                    hA[q] = fma2(v.y, w10, hA[q]);
                    hB[q] = fma2(v.y, w11, hB[q]);
                }
            }
            #pragma unroll
            for (int q = 0; q < 8; q++) {
                float a, b;
                upk2(hA[q], a, b); F2 p0 = pk2(fmaxf(a, 0.0f), fmaxf(b, 0.0f));
                upk2(hB[q], a, b); F2 p1 = pk2(fmaxf(a, 0.0f), fmaxf(b, 0.0f));
                ulonglong2 st; st.x = p0; st.y = p1;
                *(ulonglong2*)&h2S[q * 64 + 2 * l] = st;
            }
        }
        __syncwarp();

        // --- heads: 64 -> 30, lane owns c = l (weights in registers) ---
        {
            F2 hd[8];
            #pragma unroll
            for (int q = 0; q < 8; q++) hd[q] = HBd;
            #pragma unroll 2
            for (int jj = 0; jj < 32; jj++) {
                const int j = jj * 2;
                F2 w0 = dup2(HWreg[j]);
                F2 w1 = dup2(HWreg[j + 1]);
                #pragma unroll
                for (int q = 0; q < 8; q++) {
                    ulonglong2 v = *(const ulonglong2*)&h2S[q * 64 + j];
                    hd[q] = fma2(v.x, w0, hd[q]);
                    hd[q] = fma2(v.y, w1, hd[q]);
                }
            }
            #pragma unroll
            for (int q = 0; q < 8; q++) hdS[q * 32 + l] = hd[q];
        }
        __syncwarp();

        // ===== mixture: 32 lanes, 2 lanes per row, 5 comps each =====
        {
            const float xt_m = xSf[(step_m + 1) * 4 + sr_m];
            float ck[5], ak[5];
            float cmax = -1e30f, amax = -1e30f;
            #pragma unroll
            for (int k = 0; k < 5; k++) {
                float mu = hdf[hd_base + (kb_m + k) * 2];
                float sg = hdf[hd_base + (10 + kb_m + k) * 2];
                float al = hdf[hd_base + (20 + kb_m + k) * 2];
                float z = (xt_m - mu) * __expf(-sg);
                float cc = fmaf(z, -0.5f * z, al - sg) - HALF_LOG2PI;
                ck[k] = cc; ak[k] = al;
                cmax = fmaxf(cmax, cc); amax = fmaxf(amax, al);
            }
            cmax = fmaxf(cmax, __shfl_xor_sync(FULL, cmax, 1));
            amax = fmaxf(amax, __shfl_xor_sync(FULL, amax, 1));
            float sc = 0.0f, sa = 0.0f;
            #pragma unroll
            for (int k = 0; k < 5; k++) {
                sc += __expf(ck[k] - cmax);
                sa += __expf(ak[k] - amax);
            }
            sc += __shfl_xor_sync(FULL, sc, 1);
            sa += __shfl_xor_sync(FULL, sa, 1);
            res += (cmax + __logf(sc)) - (amax + __logf(sa));
        }
        __syncwarp();
    }

    // final reduce over the 4 step-slots (lanes l, l^8, l^16, l^24 share a seq)
    res += __shfl_xor_sync(FULL, res, 8);
    res += __shfl_xor_sync(FULL, res, 16);
    if (l < 8 && (l & 1) == 0) out[n0 + (l >> 1)] = expf(res);
}

extern "C" void kernel_launch(void* const* d_in, const int* in_sizes, int n_in,
                              void* d_out, int out_size) {
    const float* x      = (const float*)d_in[0];
    const float* enc1_w = (const float*)d_in[1];
    const float* enc1_b = (const float*)d_in[2];
    const float* enc2_w = (const float*)d_in[3];
    const float* enc2_b = (const float*)d_in[4];
    const float* A      = (const float*)d_in[5];
    const float* init_w = (const float*)d_in[6];
    const float* n1w    = (const float*)d_in[7];
    const float* n1b    = (const float*)d_in[8];
    const float* n2w    = (const float*)d_in[9];
    const float* n2b    = (const float*)d_in[10];
    const float* mu_w   = (const float*)d_in[11];
    const float* mu_b   = (const float*)d_in[12];
    const float* sg_w   = (const float*)d_in[13];
    const float* sg_b   = (const float*)d_in[14];
    const float* al_w   = (const float*)d_in[15];
    const float* al_b   = (const float*)d_in[16];
    float* out = (float*)d_out;

    const int smem_bytes = SMEM_FLOATS * (int)sizeof(float);
    cudaFuncSetAttribute(wfa_kernel, cudaFuncAttributeMaxDynamicSharedMemorySize, smem_bytes);
    wfa_kernel<<<NBLOCKS, THREADS, smem_bytes>>>(
        x, enc1_w, enc1_b, enc2_w, enc2_b, A, init_w,
        n1w, n1b, n2w, n2b, mu_w, mu_b, sg_w, sg_b, al_w, al_b, out);
}

// round 7
// speedup vs baseline: 3.3087x; 1.0514x over previous
#include <cuda_runtime.h>
#include <math.h>

#define THREADS 256
#define NBLOCKS 128
#define T 128

typedef unsigned long long F2;

__device__ __forceinline__ F2 pk2(float lo, float hi) {
    F2 r; asm("mov.b64 %0,{%1,%2};" : "=l"(r) : "f"(lo), "f"(hi)); return r;
}
__device__ __forceinline__ void upk2(F2 v, float& lo, float& hi) {
    asm("mov.b64 {%0,%1},%2;" : "=f"(lo), "=f"(hi) : "l"(v));
}
__device__ __forceinline__ F2 fma2(F2 a, F2 b, F2 c) {
    F2 d; asm("fma.rn.f32x2 %0,%1,%2,%3;" : "=l"(d) : "l"(a), "l"(b), "l"(c)); return d;
}
__device__ __forceinline__ F2 add2(F2 a, F2 b) {
    F2 d; asm("add.rn.f32x2 %0,%1,%2;" : "=l"(d) : "l"(a), "l"(b)); return d;
}
__device__ __forceinline__ F2 dup2(float w) { return pk2(w, w); }

__device__ __forceinline__ float tanh_fast(float x) {
    float e = __expf(2.0f * x);
    return 1.0f - __fdividef(2.0f, e + 1.0f);
}

// ---- smem float offsets ----
#define OFF_W1   0        // 2048
#define OFF_W2   2048     // 4096
#define OFF_HW   6144     // 2048  HW[j][c] pad32
#define OFF_E1W  8192     // 64
#define OFF_E1B  8256     // 64
#define OFF_E2T  8320     // 544 Enc2T[d][i] 8x68
#define OFF_E2B  8864     // 8
#define OFF_B1   8872     // 64
#define OFF_B2   8936     // 64
#define OFF_INIT 9000     // 32
#define OFF_HB   9032     // 32
#define OFF_RES  9064     // 128 [quad][warp][16]
#define W_TOT    9192

// per-quad shared (float offsets)
#define Q_TMP   0         // F2 [sp8][32]        512 f
#define Q_TH    512       // F2 [s4][sp8][32]    2048 f
#define Q_PART  2560      // F2 [p4][sp8][32]    2048 f
#define Q_E     4608      // float [s4][seq16][8] 512 f
#define Q_X     5120      // float [5][16]       80 -> pad 96
#define QUAD_SZ 5216

// per-warp private
#define P_H1 0            // F2 [q8][64]  1024 f
#define P_H2 1024         // 1024 f
#define P_HD 2048         // F2 [q8][32]  512 f
#define WARP_SZ 2560

#define SMEM_FLOATS (W_TOT + 2*QUAD_SZ + 8*WARP_SZ)

__global__ void __launch_bounds__(THREADS, 1) wfa_kernel(
    const float* __restrict__ x,
    const float* __restrict__ enc1_w, const float* __restrict__ enc1_b,
    const float* __restrict__ enc2_w, const float* __restrict__ enc2_b,
    const float* __restrict__ A_g,
    const float* __restrict__ init_w,
    const float* __restrict__ n1w, const float* __restrict__ n1b,
    const float* __restrict__ n2w, const float* __restrict__ n2b,
    const float* __restrict__ mu_w, const float* __restrict__ mu_b,
    const float* __restrict__ sg_w, const float* __restrict__ sg_b,
    const float* __restrict__ al_w, const float* __restrict__ al_b,
    float* __restrict__ out)
{
    extern __shared__ float sm[];
    const int tid = threadIdx.x;

    // ---- stage weights (A stays in registers, loaded from gmem below) ----
    for (int i = tid; i < 2048; i += THREADS) sm[OFF_W1 + i] = n1w[i];
    for (int i = tid; i < 4096; i += THREADS) sm[OFF_W2 + i] = n2w[i];
    for (int i = tid; i < 2048; i += THREADS) {
        int j = i >> 5, c = i & 31;
        float v = 0.0f;
        if (c < 10)      v = mu_w[j * 10 + c];
        else if (c < 20) v = sg_w[j * 10 + (c - 10)];
        else if (c < 30) v = al_w[j * 10 + (c - 20)];
        sm[OFF_HW + i] = v;
    }
    for (int i = tid; i < 544; i += THREADS) {
        int d = i / 68, ii = i % 68;
        sm[OFF_E2T + i] = (ii < 64) ? enc2_w[ii * 8 + d] : 0.0f;
    }
    if (tid < 64) {
        sm[OFF_E1W + tid] = enc1_w[tid];
        sm[OFF_E1B + tid] = enc1_b[tid];
        sm[OFF_B1 + tid]  = n1b[tid];
        sm[OFF_B2 + tid]  = n2b[tid];
    }
    if (tid < 8)  sm[OFF_E2B + tid]  = enc2_b[tid];
    if (tid < 32) sm[OFF_INIT + tid] = init_w[tid];
    if (tid < 32) {
        int c = tid; float v = 0.0f;
        if (c < 10)      v = mu_b[c];
        else if (c < 20) v = sg_b[c - 10];
        else if (c < 30) v = al_b[c - 20];
        sm[OFF_HB + c] = v;
    }
    __syncthreads();

    const unsigned FULL = 0xffffffffu;
    const int wid  = tid >> 5;
    const int l    = tid & 31;
    const int quad = wid >> 2;         // 0..1
    const int p    = wid & 3;          // warp within quad
    const int barid = 1 + quad;

    float* qm = sm + W_TOT + quad * QUAD_SZ;
    F2* tmpS  = (F2*)(qm + Q_TMP);     // [sp*32 + j]
    F2* thS   = (F2*)(qm + Q_TH);      // [(s*8+sp)*32 + j]
    F2* partS = (F2*)(qm + Q_PART);    // [(p*8+sp)*32 + j]
    float* eSf = qm + Q_E;             // [(s*16+seq)*8 + d]
    float* xSf = qm + Q_X;             // [slot*16 + seq]

    float* wm = sm + W_TOT + 2 * QUAD_SZ + wid * WARP_SZ;
    F2* h1S = (F2*)(wm + P_H1);
    F2* h2S = (F2*)(wm + P_H2);
    F2* hdS = (F2*)(wm + P_HD);
    float* hdf = (float*)hdS;

    // ---- register caches ----
    // A octet, d-packed: Areg2[k][dp] = (A[8p+k][2dp][l], A[8p+k][2dp+1][l])
    F2 Areg2[8][4];
    #pragma unroll
    for (int k = 0; k < 8; k++) {
        const int i = p * 8 + k;
        #pragma unroll
        for (int dp = 0; dp < 4; dp++) {
            float a0 = __ldg(&A_g[i * 256 + (2 * dp) * 32 + l]);
            float a1 = __ldg(&A_g[i * 256 + (2 * dp + 1) * 32 + l]);
            Areg2[k][dp] = pk2(a0, a1);
        }
    }
    float HWreg[64];
    #pragma unroll
    for (int j = 0; j < 64; j++) HWreg[j] = sm[OFF_HW + j * 32 + l];
    const F2 B1a = dup2(sm[OFF_B1 + 2 * l]);
    const F2 B1b = dup2(sm[OFF_B1 + 2 * l + 1]);
    const F2 B2a = dup2(sm[OFF_B2 + 2 * l]);
    const F2 B2b = dup2(sm[OFF_B2 + 2 * l + 1]);
    const F2 HBd = dup2(sm[OFF_HB + l]);

    // encoder role: seq = l&3 (warp-local), d = l>>2
    const int e_sq = l & 3;
    const int e_d  = l >> 2;
    const float e2b = sm[OFF_E2B + e_d];

    // mixture role: r_m = quad-seq 0..15, kh = l&1
    const int r_m  = l >> 1;
    const int kb_m = (l & 1) * 5;
    const int hd_base = (r_m >> 1) * 64 + (r_m & 1);

    const int n0 = blockIdx.x * 32 + quad * 16;
    const float HALF_LOG2PI = 0.9189385332046727f;

    // ---- init state: warp p owns sp = 2p, 2p+1 ----
    F2 tmpP[2];
    {
        float iv = sm[OFF_INIT + l];
        tmpP[0] = dup2(iv); tmpP[1] = tmpP[0];
        tmpS[(2 * p) * 32 + l]     = tmpP[0];
        tmpS[(2 * p + 1) * 32 + l] = tmpP[1];
    }

    float res = 0.0f;
    float xlast = 0.0f;

    #pragma unroll 1
    for (int it = 0; it < 32; it++) {
        // window-start barrier: prev window's phi/mixture reads done before we
        // overwrite xSf/eSf; also makes tmp-init visible on it=0.
        asm volatile("bar.sync %0, 128;" :: "r"(barid) : "memory");

        // ---- stage x for window: slots 0..4 = x[it*4-1 .. it*4+3] ----
        if (l < 4) xSf[4 * p + l] = xlast;
        if (l < 16) {
            int s = l >> 2, sq = l & 3;
            xSf[(s + 1) * 16 + 4 * p + sq] =
                __ldg(&x[(size_t)(n0 + 4 * p + sq) * T + it * 4 + s]);
        }
        __syncwarp();
        if (l < 4) xlast = xSf[4 * 16 + 4 * p + l];

        // ---- encoder batched over 4 steps (warp-local seqs) ----
        {
            float xe0 = xSf[0 * 16 + 4 * p + e_sq];
            float xe1 = xSf[1 * 16 + 4 * p + e_sq];
            float xe2 = xSf[2 * 16 + 4 * p + e_sq];
            float xe3 = xSf[3 * 16 + 4 * p + e_sq];
            float a0 = 0.f, a1 = 0.f, a2 = 0.f, a3 = 0.f;
            const float* Et = sm + OFF_E2T + e_d * 68;
            #pragma unroll 4
            for (int i = 0; i < 64; i += 4) {
                float4 w  = *(const float4*)&sm[OFF_E1W + i];
                float4 b  = *(const float4*)&sm[OFF_E1B + i];
                float4 tv = *(const float4*)&Et[i];
                float h;
                h = fmaxf(fmaf(xe0,w.x,b.x),0.f); a0 = fmaf(h,tv.x,a0);
                h = fmaxf(fmaf(xe1,w.x,b.x),0.f); a1 = fmaf(h,tv.x,a1);
                h = fmaxf(fmaf(xe2,w.x,b.x),0.f); a2 = fmaf(h,tv.x,a2);
                h = fmaxf(fmaf(xe3,w.x,b.x),0.f); a3 = fmaf(h,tv.x,a3);
                h = fmaxf(fmaf(xe0,w.y,b.y),0.f); a0 = fmaf(h,tv.y,a0);
                h = fmaxf(fmaf(xe1,w.y,b.y),0.f); a1 = fmaf(h,tv.y,a1);
                h = fmaxf(fmaf(xe2,w.y,b.y),0.f); a2 = fmaf(h,tv.y,a2);
                h = fmaxf(fmaf(xe3,w.y,b.y),0.f); a3 = fmaf(h,tv.y,a3);
                h = fmaxf(fmaf(xe0,w.z,b.z),0.f); a0 = fmaf(h,tv.z,a0);
                h = fmaxf(fmaf(xe1,w.z,b.z),0.f); a1 = fmaf(h,tv.z,a1);
                h = fmaxf(fmaf(xe2,w.z,b.z),0.f); a2 = fmaf(h,tv.z,a2);
                h = fmaxf(fmaf(xe3,w.z,b.z),0.f); a3 = fmaf(h,tv.z,a3);
                h = fmaxf(fmaf(xe0,w.w,b.w),0.f); a0 = fmaf(h,tv.w,a0);
                h = fmaxf(fmaf(xe1,w.w,b.w),0.f); a1 = fmaf(h,tv.w,a1);
                h = fmaxf(fmaf(xe2,w.w,b.w),0.f); a2 = fmaf(h,tv.w,a2);
                h = fmaxf(fmaf(xe3,w.w,b.w),0.f); a3 = fmaf(h,tv.w,a3);
            }
            const int eb = (4 * p + e_sq) * 8 + e_d;
            eSf[0 * 128 + eb] = tanh_fast(a0 + e2b);
            eSf[1 * 128 + eb] = tanh_fast(a1 + e2b);
            eSf[2 * 128 + eb] = tanh_fast(a2 + e2b);
            eSf[3 * 128 + eb] = tanh_fast(a3 + e2b);
        }
        asm volatile("bar.sync %0, 128;" :: "r"(barid) : "memory");

        // ---- 4 sequential micro-steps ----
        #pragma unroll 1
        for (int s = 0; s < 4; s++) {
            if (it * 4 + s > 0) {
                // i-partial, e-combined update for ALL 8 seq-pairs
                #pragma unroll 1
                for (int sp = 0; sp < 8; sp++) {
                    const F2* tr = &tmpS[sp * 32 + 8 * p];
                    ulonglong2 t0 = *(const ulonglong2*)&tr[0];
                    ulonglong2 t1 = *(const ulonglong2*)&tr[2];
                    ulonglong2 t2 = *(const ulonglong2*)&tr[4];
                    ulonglong2 t3 = *(const ulonglong2*)&tr[6];
                    F2 tF[8] = {t0.x,t0.y,t1.x,t1.y,t2.x,t2.y,t3.x,t3.y};
                    F2 ua0=0,ua1=0,ua2=0,ua3=0,ub0=0,ub1=0,ub2=0,ub3=0;
                    #pragma unroll
                    for (int k = 0; k < 8; k++) {
                        float ta, tb; upk2(tF[k], ta, tb);
                        F2 da = dup2(ta), db = dup2(tb);
                        ua0 = fma2(da, Areg2[k][0], ua0);
                        ua1 = fma2(da, Areg2[k][1], ua1);
                        ua2 = fma2(da, Areg2[k][2], ua2);
                        ua3 = fma2(da, Areg2[k][3], ua3);
                        ub0 = fma2(db, Areg2[k][0], ub0);
                        ub1 = fma2(db, Areg2[k][1], ub1);
                        ub2 = fma2(db, Areg2[k][2], ub2);
                        ub3 = fma2(db, Areg2[k][3], ub3);
                    }
                    const float* ea = &eSf[(s * 16 + 2 * sp) * 8];
                    ulonglong2 ev0 = *(const ulonglong2*)&ea[0];
                    ulonglong2 ev1 = *(const ulonglong2*)&ea[4];
                    ulonglong2 fv0 = *(const ulonglong2*)&ea[8];
                    ulonglong2 fv1 = *(const ulonglong2*)&ea[12];
                    F2 wa = 0, wb = 0;
                    wa = fma2(ev0.x, ua0, wa); wa = fma2(ev0.y, ua1, wa);
                    wa = fma2(ev1.x, ua2, wa); wa = fma2(ev1.y, ua3, wa);
                    wb = fma2(fv0.x, ub0, wb); wb = fma2(fv0.y, ub1, wb);
                    wb = fma2(fv1.x, ub2, wb); wb = fma2(fv1.y, ub3, wb);
                    float wa0, wa1, wb0, wb1;
                    upk2(wa, wa0, wa1); upk2(wb, wb0, wb1);
                    partS[(p * 8 + sp) * 32 + l] = pk2(wa0 + wa1, wb0 + wb1);
                }
                asm volatile("bar.sync %0, 128;" :: "r"(barid) : "memory");
                // combine my 2 sp rows
                #pragma unroll
                for (int b = 0; b < 2; b++) {
                    const int sp = 2 * p + b;
                    F2 v0 = add2(partS[(0 * 8 + sp) * 32 + l],
                                 partS[(1 * 8 + sp) * 32 + l]);
                    F2 v1 = add2(partS[(2 * 8 + sp) * 32 + l],
                                 partS[(3 * 8 + sp) * 32 + l]);
                    tmpP[b] = add2(v0, v1);
                }
            }
            // publish tmp + tanh(tmp) into this step's th slot
            #pragma unroll
            for (int b = 0; b < 2; b++) {
                const int sp = 2 * p + b;
                tmpS[sp * 32 + l] = tmpP[b];
                float ta, tb; upk2(tmpP[b], ta, tb);
                thS[(s * 8 + sp) * 32 + l] = pk2(tanh_fast(ta), tanh_fast(tb));
            }
            asm volatile("bar.sync %0, 128;" :: "r"(barid) : "memory");
        }

        // ===== phi batched: warp p processes step p's 16 rows (8 q-pairs) =====
        const F2* thB = thS + p * 256;

        // --- W1: 32 -> 64, lane owns o = 2l, 2l+1 ---
        {
            F2 hA[8], hB[8];
            #pragma unroll
            for (int q = 0; q < 8; q++) { hA[q] = B1a; hB[q] = B1b; }
            #pragma unroll 2
            for (int ii = 0; ii < 16; ii++) {
                const int i = ii * 2;
                float2 w0 = *(const float2*)&sm[OFF_W1 + i * 64 + 2 * l];
                float2 w1 = *(const float2*)&sm[OFF_W1 + (i + 1) * 64 + 2 * l];
                F2 w00 = dup2(w0.x), w01 = dup2(w0.y), w10 = dup2(w1.x), w11 = dup2(w1.y);
                #pragma unroll
                for (int q = 0; q < 8; q++) {
                    ulonglong2 v = *(const ulonglong2*)&thB[q * 32 + i];
                    hA[q] = fma2(v.x, w00, hA[q]);
                    hB[q] = fma2(v.x, w01, hB[q]);
                    hA[q] = fma2(v.y, w10, hA[q]);
                    hB[q] = fma2(v.y, w11, hB[q]);
                }
            }
            #pragma unroll
            for (int q = 0; q < 8; q++) {
                float a, b;
                upk2(hA[q], a, b); F2 p0 = pk2(fmaxf(a, 0.f), fmaxf(b, 0.f));
                upk2(hB[q], a, b); F2 p1 = pk2(fmaxf(a, 0.f), fmaxf(b, 0.f));
                ulonglong2 st; st.x = p0; st.y = p1;
                *(ulonglong2*)&h1S[q * 64 + 2 * l] = st;
            }
        }
        __syncwarp();

        // --- W2: 64 -> 64 ---
        {
            F2 hA[8], hB[8];
            #pragma unroll
            for (int q = 0; q < 8; q++) { hA[q] = B2a; hB[q] = B2b; }
            #pragma unroll 2
            for (int kk = 0; kk < 32; kk++) {
                const int k = kk * 2;
                float2 w0 = *(const float2*)&sm[OFF_W2 + k * 64 + 2 * l];
                float2 w1 = *(const float2*)&sm[OFF_W2 + (k + 1) * 64 + 2 * l];
                F2 w00 = dup2(w0.x), w01 = dup2(w0.y), w10 = dup2(w1.x), w11 = dup2(w1.y);
                #pragma unroll
                for (int q = 0; q < 8; q++) {
                    ulonglong2 v = *(const ulonglong2*)&h1S[q * 64 + k];
                    hA[q] = fma2(v.x, w00, hA[q]);
                    hB[q] = fma2(v.x, w01, hB[q]);
                    hA[q] = fma2(v.y, w10, hA[q]);
                    hB[q] = fma2(v.y, w11, hB[q]);
                }
            }
            #pragma unroll
            for (int q = 0; q < 8; q++) {
                float a, b;
                upk2(hA[q], a, b); F2 p0 = pk2(fmaxf(a, 0.f), fmaxf(b, 0.f));
                upk2(hB[q], a, b); F2 p1 = pk2(fmaxf(a, 0.f), fmaxf(b, 0.f));
                ulonglong2 st; st.x = p0; st.y = p1;
                *(ulonglong2*)&h2S[q * 64 + 2 * l] = st;
            }
        }
        __syncwarp();

        // --- heads: 64 -> 30, lane owns c = l (weights in registers) ---
        {
            F2 hd[8];
            #pragma unroll
            for (int q = 0; q < 8; q++) hd[q] = HBd;
            #pragma unroll 2
            for (int jj = 0; jj < 32; jj++) {
                const int j = jj * 2;
                F2 w0 = dup2(HWreg[j]);
                F2 w1 = dup2(HWreg[j + 1]);
                #pragma unroll
                for (int q = 0; q < 8; q++) {
                    ulonglong2 v = *(const ulonglong2*)&h2S[q * 64 + j];
                    hd[q] = fma2(v.x, w0, hd[q]);
                    hd[q] = fma2(v.y, w1, hd[q]);
                }
            }
            #pragma unroll
            for (int q = 0; q < 8; q++) hdS[q * 32 + l] = hd[q];
        }
        __syncwarp();

        // ===== mixture: step p, 16 quad-seqs, 2 lanes/seq, 5 comps each =====
        {
            const float xt_m = xSf[(p + 1) * 16 + r_m];
            float ck[5], ak[5];
            float cmax = -1e30f, amax = -1e30f;
            #pragma unroll
            for (int k = 0; k < 5; k++) {
                float mu = hdf[hd_base + (kb_m + k) * 2];
                float sg = hdf[hd_base + (10 + kb_m + k) * 2];
                float al = hdf[hd_base + (20 + kb_m + k) * 2];
                float z = (xt_m - mu) * __expf(-sg);
                float cc = fmaf(z, -0.5f * z, al - sg) - HALF_LOG2PI;
                ck[k] = cc; ak[k] = al;
                cmax = fmaxf(cmax, cc); amax = fmaxf(amax, al);
            }
            cmax = fmaxf(cmax, __shfl_xor_sync(FULL, cmax, 1));
            amax = fmaxf(amax, __shfl_xor_sync(FULL, amax, 1));
            float sc = 0.0f, sa = 0.0f;
            #pragma unroll
            for (int k = 0; k < 5; k++) {
                sc += __expf(ck[k] - cmax);
                sa += __expf(ak[k] - amax);
            }
            sc += __shfl_xor_sync(FULL, sc, 1);
            sa += __shfl_xor_sync(FULL, sa, 1);
            res += (cmax + __logf(sc)) - (amax + __logf(sa));
        }
    }

    // ---- final cross-warp reduction of per-step log-density partials ----
    if ((l & 1) == 0) sm[OFF_RES + (quad * 4 + p) * 16 + (l >> 1)] = res;
    __syncthreads();
    if (tid < 32) {
        int qd = tid >> 4, sq = tid & 15;
        const float* rb = sm + OFF_RES + qd * 64;
        out[blockIdx.x * 32 + qd * 16 + sq] =
            expf(rb[0 * 16 + sq] + rb[1 * 16 + sq] + rb[2 * 16 + sq] + rb[3 * 16 + sq]);
    }
}

extern "C" void kernel_launch(void* const* d_in, const int* in_sizes, int n_in,
                              void* d_out, int out_size) {
    const float* x      = (const float*)d_in[0];
    const float* enc1_w = (const float*)d_in[1];
    const float* enc1_b = (const float*)d_in[2];
    const float* enc2_w = (const float*)d_in[3];
    const float* enc2_b = (const float*)d_in[4];
    const float* A      = (const float*)d_in[5];
    const float* init_w = (const float*)d_in[6];
    const float* n1w    = (const float*)d_in[7];
    const float* n1b    = (const float*)d_in[8];
    const float* n2w    = (const float*)d_in[9];
    const float* n2b    = (const float*)d_in[10];
    const float* mu_w   = (const float*)d_in[11];
    const float* mu_b   = (const float*)d_in[12];
    const float* sg_w   = (const float*)d_in[13];
    const float* sg_b   = (const float*)d_in[14];
    const float* al_w   = (const float*)d_in[15];
    const float* al_b   = (const float*)d_in[16];
    float* out = (float*)d_out;

    const int smem_bytes = SMEM_FLOATS * (int)sizeof(float);
    cudaFuncSetAttribute(wfa_kernel, cudaFuncAttributeMaxDynamicSharedMemorySize, smem_bytes);
    wfa_kernel<<<NBLOCKS, THREADS, smem_bytes>>>(
        x, enc1_w, enc1_b, enc2_w, enc2_b, A, init_w,
        n1w, n1b, n2w, n2b, mu_w, mu_b, sg_w, sg_b, al_w, al_b, out);
}